// round 7
// baseline (speedup 1.0000x reference)
#include <cuda_runtime.h>
#include <cuda_bf16.h>
#include <cstdint>

#define NB 4
#define SQ 1024
#define DM 1280
#define NH 16
#define HD 80
#define MTOT (NB*SQ)      // 4096
#define NQKV (3*DM)       // 3840

// ---------------------------------------------------------------------------
// Scratch (__device__ globals; allocation-free rule)
// ---------------------------------------------------------------------------
__device__ float g_q[NB*NH*SQ*HD];
__device__ float g_k[NB*NH*SQ*HD];

__device__ __nv_bfloat16 xh_g[MTOT*DM],  xl_g[MTOT*DM];
__device__ __nv_bfloat16 wqh_g[NQKV*DM], wql_g[NQKV*DM];
__device__ __nv_bfloat16 wph_g[DM*DM],   wpl_g[DM*DM];
__device__ __nv_bfloat16 qh_g[NB*NH*SQ*HD], ql_g[NB*NH*SQ*HD];
__device__ __nv_bfloat16 kh_g[NB*NH*SQ*HD], kl_g[NB*NH*SQ*HD];
__device__ __nv_bfloat16 vh_g[NB*NH*SQ*HD], vl_g[NB*NH*SQ*HD];
__device__ __nv_bfloat16 ch_g[MTOT*DM],  cl_g[MTOT*DM];

// ---------------------------------------------------------------------------
// helpers
// ---------------------------------------------------------------------------
__device__ __forceinline__ uint32_t s2u(const void* p) {
    uint32_t a;
    asm("{ .reg .u64 t; cvta.to.shared.u64 t, %1; cvt.u32.u64 %0, t; }"
        : "=r"(a) : "l"(p));
    return a;
}
__device__ __forceinline__ void ldm_x4(uint32_t* r, uint32_t addr) {
    asm volatile("ldmatrix.sync.aligned.m8n8.x4.shared.b16 {%0,%1,%2,%3}, [%4];"
        : "=r"(r[0]), "=r"(r[1]), "=r"(r[2]), "=r"(r[3]) : "r"(addr));
}
__device__ __forceinline__ void ldm_x4_t(uint32_t* r, uint32_t addr) {
    asm volatile("ldmatrix.sync.aligned.m8n8.x4.trans.shared.b16 {%0,%1,%2,%3}, [%4];"
        : "=r"(r[0]), "=r"(r[1]), "=r"(r[2]), "=r"(r[3]) : "r"(addr));
}
__device__ __forceinline__ void mma16816(float* c, const uint32_t* a,
                                         uint32_t b0, uint32_t b1) {
    asm volatile(
        "mma.sync.aligned.m16n8k16.row.col.f32.bf16.bf16.f32 "
        "{%0,%1,%2,%3}, {%4,%5,%6,%7}, {%8,%9}, {%0,%1,%2,%3};"
        : "+f"(c[0]), "+f"(c[1]), "+f"(c[2]), "+f"(c[3])
        : "r"(a[0]), "r"(a[1]), "r"(a[2]), "r"(a[3]), "r"(b0), "r"(b1));
}
__device__ __forceinline__ uint32_t packbf(float a, float b) {
    __nv_bfloat162 t = __floats2bfloat162_rn(a, b);
    return *reinterpret_cast<uint32_t*>(&t);
}
__device__ __forceinline__ void cpasync16(uint32_t dst, const void* src) {
    asm volatile("cp.async.ca.shared.global [%0], [%1], 16;"
        :: "r"(dst), "l"(src) : "memory");
}
#define CP_COMMIT() asm volatile("cp.async.commit_group;" ::: "memory")
#define CP_WAIT0()  asm volatile("cp.async.wait_group 0;" ::: "memory")
#define CP_WAIT1()  asm volatile("cp.async.wait_group 1;" ::: "memory")
#define CP_WAIT2()  asm volatile("cp.async.wait_group 2;" ::: "memory")

// ---------------------------------------------------------------------------
// fp32 -> bf16 hi/lo split
// ---------------------------------------------------------------------------
__global__ void __launch_bounds__(256) split_kernel(
    const float* __restrict__ src, __nv_bfloat16* __restrict__ hi,
    __nv_bfloat16* __restrict__ lo, int n4)
{
    const int i = blockIdx.x * 256 + threadIdx.x;
    if (i >= n4) return;
    float4 v = ((const float4*)src)[i];
    __nv_bfloat16 h0 = __float2bfloat16_rn(v.x), h1 = __float2bfloat16_rn(v.y);
    __nv_bfloat16 h2 = __float2bfloat16_rn(v.z), h3 = __float2bfloat16_rn(v.w);
    ((__nv_bfloat162*)hi)[2*i+0] = __nv_bfloat162(h0, h1);
    ((__nv_bfloat162*)hi)[2*i+1] = __nv_bfloat162(h2, h3);
    ((__nv_bfloat162*)lo)[2*i+0] = __floats2bfloat162_rn(
        v.x - __bfloat162float(h0), v.y - __bfloat162float(h1));
    ((__nv_bfloat162*)lo)[2*i+1] = __floats2bfloat162_rn(
        v.z - __bfloat162float(h2), v.w - __bfloat162float(h3));
}

// ===========================================================================
// GEMM: C[m,n] = sum_k A[m,k]*W[n,k] + bias[n], pre-split bf16, mma.sync.
// Tile 128x128, K-stage 16, FOUR-stage cp.async pipeline (96KB smem),
// single barrier per iteration, 2 CTAs/SM.
// ===========================================================================
#define KSTAGE 16
#define NIT (DM / KSTAGE)          // 80
#define PITCH 48                   // 32B data + 16B pad
#define MAT_BYTES (128 * PITCH)    // 6144
#define STAGE_BYTES (4 * MAT_BYTES)    // 24576
#define GEMM_DSMEM (4 * STAGE_BYTES)   // 98304

template<bool QKV>
__global__ void __launch_bounds__(256, 2) gemm_bf16(
    const __nv_bfloat16* __restrict__ Ah_g, const __nv_bfloat16* __restrict__ Al_g,
    const __nv_bfloat16* __restrict__ Bh_g, const __nv_bfloat16* __restrict__ Bl_g,
    const float* __restrict__ bias, float* __restrict__ Cout)
{
    extern __shared__ char dsm_raw[];
    const uint32_t base = s2u(dsm_raw);

    const int tid  = threadIdx.x;
    const int wid  = tid >> 5, lane = tid & 31;
    const int bx = blockIdx.x, by = blockIdx.y;
    const int wm = wid >> 1, wn = wid & 1;      // warp tile: 32(M) x 64(N)

    const __nv_bfloat16* bases[4] = {
        Ah_g + (size_t)(by * 128) * DM, Al_g + (size_t)(by * 128) * DM,
        Bh_g + (size_t)(bx * 128) * DM, Bl_g + (size_t)(bx * 128) * DM };

    auto ISSUE = [&](int it) {
        const uint32_t sb = base + (it & 3) * STAGE_BYTES;
        #pragma unroll
        for (int j = 0; j < 4; j++) {
            const int idx = tid + 256 * j;       // 0..1023
            const int mat = idx >> 8;
            const int rem = idx & 255;
            const int r = rem >> 1, c = rem & 1;
            const uint32_t dst = sb + mat * MAT_BYTES + r * PITCH + c * 16;
            const __nv_bfloat16* src = bases[mat] + (size_t)r * DM + it * KSTAGE + c * 8;
            cpasync16(dst, src);
        }
        CP_COMMIT();
    };

    float acc[2][8][4];
    #pragma unroll
    for (int i = 0; i < 2; i++)
        #pragma unroll
        for (int j = 0; j < 8; j++)
            #pragma unroll
            for (int q = 0; q < 4; q++) acc[i][j][q] = 0.f;

    ISSUE(0); ISSUE(1); ISSUE(2);

    for (int it = 0; it < NIT; ++it) {
        if (it < NIT - 2)      { CP_WAIT2(); }
        else if (it == NIT - 2){ CP_WAIT1(); }
        else                   { CP_WAIT0(); }
        __syncthreads();
        if (it + 3 < NIT) ISSUE(it + 3);

        const uint32_t sb = base + (it & 3) * STAGE_BYTES;
        uint32_t Ah[2][4], Al[2][4];
        #pragma unroll
        for (int mf = 0; mf < 2; mf++) {
            const uint32_t aoff =
                (uint32_t)((wm*32 + mf*16 + (lane & 15)) * PITCH + (lane >> 4) * 16);
            ldm_x4(Ah[mf], sb + aoff);
            ldm_x4(Al[mf], sb + MAT_BYTES + aoff);
        }
        uint32_t Bh[4][4], Bl[4][4];
        #pragma unroll
        for (int g = 0; g < 4; g++) {
            const int quad = lane >> 3;
            const uint32_t boff =
                (uint32_t)((wn*64 + g*16 + (quad >> 1) * 8 + (lane & 7)) * PITCH
                           + (quad & 1) * 16);
            ldm_x4(Bh[g], sb + 2*MAT_BYTES + boff);
            ldm_x4(Bl[g], sb + 3*MAT_BYTES + boff);
        }
        #pragma unroll
        for (int mf = 0; mf < 2; mf++)
            #pragma unroll
            for (int nb = 0; nb < 8; nb++)
                mma16816(acc[mf][nb], Ah[mf], Bh[nb>>1][(nb&1)*2], Bh[nb>>1][(nb&1)*2+1]);
        #pragma unroll
        for (int mf = 0; mf < 2; mf++)
            #pragma unroll
            for (int nb = 0; nb < 8; nb++)
                mma16816(acc[mf][nb], Al[mf], Bh[nb>>1][(nb&1)*2], Bh[nb>>1][(nb&1)*2+1]);
        #pragma unroll
        for (int mf = 0; mf < 2; mf++)
            #pragma unroll
            for (int nb = 0; nb < 8; nb++)
                mma16816(acc[mf][nb], Ah[mf], Bl[nb>>1][(nb&1)*2], Bl[nb>>1][(nb&1)*2+1]);
    }

    // Epilogue
    #pragma unroll
    for (int mf = 0; mf < 2; mf++)
        #pragma unroll
        for (int nb = 0; nb < 8; nb++)
            #pragma unroll
            for (int ci = 0; ci < 2; ci++) {
                const int m = by*128 + wm*32 + mf*16 + (lane >> 2) + ci*8;
                const int n = bx*128 + wn*64 + nb*8 + (lane & 3) * 2;
                float2 v;
                v.x = acc[mf][nb][2*ci+0] + bias[n];
                v.y = acc[mf][nb][2*ci+1] + bias[n+1];
                if (QKV) {
                    const int sel = n / DM;
                    const int r2  = n - sel * DM;
                    const int h   = r2 / HD;
                    const int dd  = r2 - h * HD;
                    const int bb  = m >> 10;
                    const int ss  = m & (SQ - 1);
                    const size_t di = (((size_t)bb * NH + h) * SQ + ss) * HD + dd;
                    if (sel == 0)      *(float2*)&g_q[di] = v;
                    else if (sel == 1) *(float2*)&g_k[di] = v;
                    else {
                        __nv_bfloat16 h0 = __float2bfloat16_rn(v.x);
                        __nv_bfloat16 h1 = __float2bfloat16_rn(v.y);
                        *(__nv_bfloat162*)&vh_g[di] = __nv_bfloat162(h0, h1);
                        *(__nv_bfloat162*)&vl_g[di] = __floats2bfloat162_rn(
                            v.x - __bfloat162float(h0), v.y - __bfloat162float(h1));
                    }
                } else {
                    *(float2*)&Cout[(size_t)m * DM + n] = v;
                }
            }
}

// ---------------------------------------------------------------------------
// RoPE: read g_q/g_k fp32, write rotated bf16 hi/lo
// ---------------------------------------------------------------------------
__global__ void __launch_bounds__(256) rope_kernel(
    const float* __restrict__ cosp, const float* __restrict__ sinp)
{
    const int idx  = blockIdx.x * 256 + threadIdx.x;   // < NB*NH*SQ*40
    const int d    = idx % 40;
    const int rest = idx / 40;
    const int ss   = rest & (SQ - 1);
    const int bh   = rest >> 10;
    const size_t base = ((size_t)bh * SQ + ss) * HD;
    const float c1 = cosp[ss*HD + d],      s1 = sinp[ss*HD + d];
    const float c2 = cosp[ss*HD + d + 40], s2 = sinp[ss*HD + d + 40];

    float q1 = g_q[base + d], q2 = g_q[base + d + 40];
    float o1 = q1*c1 - q2*s1;
    float o2 = q2*c2 + q1*s2;
    __nv_bfloat16 h;
    h = __float2bfloat16_rn(o1); qh_g[base+d]    = h; ql_g[base+d]    = __float2bfloat16_rn(o1 - __bfloat162float(h));
    h = __float2bfloat16_rn(o2); qh_g[base+d+40] = h; ql_g[base+d+40] = __float2bfloat16_rn(o2 - __bfloat162float(h));

    float k1 = g_k[base + d], k2 = g_k[base + d + 40];
    o1 = k1*c1 - k2*s1;
    o2 = k2*c2 + k1*s2;
    h = __float2bfloat16_rn(o1); kh_g[base+d]    = h; kl_g[base+d]    = __float2bfloat16_rn(o1 - __bfloat162float(h));
    h = __float2bfloat16_rn(o2); kh_g[base+d+40] = h; kl_g[base+d+40] = __float2bfloat16_rn(o2 - __bfloat162float(h));
}

// ===========================================================================
// Flash attention on mma.sync. CTA = (q-tile 128 rows, bh), 8 warps (256 thr).
// Double-buffered K/V via cp.async; single barrier per iteration.
// ===========================================================================
#define APITCH 176                        // bytes per 80-elem bf16 row (+pad)
#define AMATQ (128*APITCH)                // 22528 per Q matrix (128 rows)
#define AMAT64 (64*APITCH)                // 11264 per KV matrix (64 rows)
#define AQH 0
#define AQL AMATQ
#define AKV0 (2*AMATQ)                    // 45056
#define KV_STAGE (4*AMAT64)               // 45056
#define ATTN_SMEM (2*AMATQ + 2*KV_STAGE)  // 135168

__global__ void __launch_bounds__(256) attn_tc()
{
    extern __shared__ char dsm_raw[];
    const uint32_t base = s2u(dsm_raw);

    const int tid = threadIdx.x;
    const int w = tid >> 5, lane = tid & 31;
    const int qt = blockIdx.x, bh = blockIdx.y;
    const int b = bh >> 4, h = bh & 15;
    const float scale = 0.11180339887498948f;  // 1/sqrt(80)

    const size_t krow0base = (size_t)bh * SQ;

    auto ISSUE_KV = [&](int kt) {
        const uint32_t sb = base + AKV0 + (kt & 1) * KV_STAGE;
        const size_t krow0 = krow0base + kt * 64;
        const __nv_bfloat16* srcs[4] = { kh_g, kl_g, vh_g, vl_g };
        #pragma unroll
        for (int j = 0; j < 10; j++) {
            const int idx = tid + 256 * j;   // 0..2559
            const int mat = idx / 640;
            const int rem = idx - mat * 640;
            const int r = rem / 10, c = rem - r * 10;
            cpasync16(sb + mat * AMAT64 + r * APITCH + c * 16,
                      srcs[mat] + (krow0 + r) * HD + c * 8);
        }
        CP_COMMIT();
    };

    // Q tile load (once): 128 rows x 10 chunks x 2 matrices = 2560
    {
        const size_t qrow0 = krow0base + qt * 128;
        #pragma unroll
        for (int j = 0; j < 10; j++) {
            const int idx = tid + 256 * j;
            const int mat = idx / 1280;
            const int rem = idx - mat * 1280;
            const int r = rem / 10, c = rem - r * 10;
            cpasync16(base + (mat ? AQL : AQH) + r * APITCH + c * 16,
                      (mat ? ql_g : qh_g) + (qrow0 + r) * HD + c * 8);
        }
        CP_COMMIT();
    }
    ISSUE_KV(0);

    float oacc[10][4];
    #pragma unroll
    for (int i = 0; i < 10; i++)
        #pragma unroll
        for (int j = 0; j < 4; j++) oacc[i][j] = 0.f;
    float m0 = -1e30f, m1 = -1e30f, l0 = 0.f, l1 = 0.f;

    for (int kt = 0; kt < 16; kt++) {
        CP_WAIT0();
        __syncthreads();
        if (kt + 1 < 16) ISSUE_KV(kt + 1);

        const uint32_t kvb = base + AKV0 + (kt & 1) * KV_STAGE;
        const uint32_t sKH = kvb, sKL = kvb + AMAT64;
        const uint32_t sVH = kvb + 2*AMAT64, sVL = kvb + 3*AMAT64;

        // ---- S = Q K^T (16x64 per warp), 3-pass split ----
        float sacc[8][4];
        #pragma unroll
        for (int i = 0; i < 8; i++)
            #pragma unroll
            for (int j = 0; j < 4; j++) sacc[i][j] = 0.f;

        #pragma unroll
        for (int kc = 0; kc < 5; kc++) {
            uint32_t Aah[4], Aal[4];
            const uint32_t aoff =
                (uint32_t)((w*16 + (lane & 15)) * APITCH + kc*32 + (lane >> 4) * 16);
            ldm_x4(Aah, base + AQH + aoff);
            ldm_x4(Aal, base + AQL + aoff);
            uint32_t Bh4[4][4], Bl4[4][4];
            #pragma unroll
            for (int g = 0; g < 4; g++) {
                const int quad = lane >> 3;
                const uint32_t boff =
                    (uint32_t)((g*16 + (quad >> 1) * 8 + (lane & 7)) * APITCH
                               + kc*32 + (quad & 1) * 16);
                ldm_x4(Bh4[g], sKH + boff);
                ldm_x4(Bl4[g], sKL + boff);
            }
            #pragma unroll
            for (int g = 0; g < 4; g++)
                #pragma unroll
                for (int hh = 0; hh < 2; hh++)
                    mma16816(sacc[g*2+hh], Aah, Bh4[g][2*hh], Bh4[g][2*hh+1]);
            #pragma unroll
            for (int g = 0; g < 4; g++)
                #pragma unroll
                for (int hh = 0; hh < 2; hh++)
                    mma16816(sacc[g*2+hh], Aal, Bh4[g][2*hh], Bh4[g][2*hh+1]);
            #pragma unroll
            for (int g = 0; g < 4; g++)
                #pragma unroll
                for (int hh = 0; hh < 2; hh++)
                    mma16816(sacc[g*2+hh], Aah, Bl4[g][2*hh], Bl4[g][2*hh+1]);
        }

        // ---- online softmax on fragments ----
        #pragma unroll
        for (int nb = 0; nb < 8; nb++)
            #pragma unroll
            for (int j = 0; j < 4; j++) sacc[nb][j] *= scale;

        float mx0 = -1e30f, mx1 = -1e30f;
        #pragma unroll
        for (int nb = 0; nb < 8; nb++) {
            mx0 = fmaxf(mx0, fmaxf(sacc[nb][0], sacc[nb][1]));
            mx1 = fmaxf(mx1, fmaxf(sacc[nb][2], sacc[nb][3]));
        }
        mx0 = fmaxf(mx0, __shfl_xor_sync(0xffffffffu, mx0, 1));
        mx0 = fmaxf(mx0, __shfl_xor_sync(0xffffffffu, mx0, 2));
        mx1 = fmaxf(mx1, __shfl_xor_sync(0xffffffffu, mx1, 1));
        mx1 = fmaxf(mx1, __shfl_xor_sync(0xffffffffu, mx1, 2));

        const float mn0 = fmaxf(m0, mx0), mn1 = fmaxf(m1, mx1);
        const float al0 = __expf(m0 - mn0), al1 = __expf(m1 - mn1);
        m0 = mn0; m1 = mn1;

        float rs0 = 0.f, rs1 = 0.f;
        #pragma unroll
        for (int nb = 0; nb < 8; nb++) {
            sacc[nb][0] = __expf(sacc[nb][0] - m0);
            sacc[nb][1] = __expf(sacc[nb][1] - m0);
            sacc[nb][2] = __expf(sacc[nb][2] - m1);
            sacc[nb][3] = __expf(sacc[nb][3] - m1);
            rs0 += sacc[nb][0] + sacc[nb][1];
            rs1 += sacc[nb][2] + sacc[nb][3];
        }
        rs0 += __shfl_xor_sync(0xffffffffu, rs0, 1);
        rs0 += __shfl_xor_sync(0xffffffffu, rs0, 2);
        rs1 += __shfl_xor_sync(0xffffffffu, rs1, 1);
        rs1 += __shfl_xor_sync(0xffffffffu, rs1, 2);
        l0 = l0 * al0 + rs0;
        l1 = l1 * al1 + rs1;

        #pragma unroll
        for (int nb = 0; nb < 10; nb++) {
            oacc[nb][0] *= al0; oacc[nb][1] *= al0;
            oacc[nb][2] *= al1; oacc[nb][3] *= al1;
        }

        // ---- O += P @ V, 3-pass ----
        #pragma unroll
        for (int kc = 0; kc < 4; kc++) {
            uint32_t Pa_h[4], Pa_l[4];
            #pragma unroll
            for (int half2i = 0; half2i < 2; half2i++) {
                const int nb = 2*kc + half2i;
                float f0 = sacc[nb][0], f1 = sacc[nb][1];
                float f2 = sacc[nb][2], f3 = sacc[nb][3];
                float h0 = __bfloat162float(__float2bfloat16_rn(f0));
                float h1 = __bfloat162float(__float2bfloat16_rn(f1));
                float h2 = __bfloat162float(__float2bfloat16_rn(f2));
                float h3 = __bfloat162float(__float2bfloat16_rn(f3));
                Pa_h[2*half2i+0] = packbf(h0, h1);
                Pa_h[2*half2i+1] = packbf(h2, h3);
                Pa_l[2*half2i+0] = packbf(f0 - h0, f1 - h1);
                Pa_l[2*half2i+1] = packbf(f2 - h2, f3 - h3);
            }
            uint32_t Vh4[5][4], Vl4[5][4];
            #pragma unroll
            for (int vg = 0; vg < 5; vg++) {
                const int vrow = kc*16 + ((lane >> 3) & 1) * 8 + (lane & 7);
                const int vcol = vg*16 + (lane >> 4) * 8;
                const uint32_t voff = (uint32_t)(vrow * APITCH + vcol * 2);
                ldm_x4_t(Vh4[vg], sVH + voff);
                ldm_x4_t(Vl4[vg], sVL + voff);
            }
            #pragma unroll
            for (int vg = 0; vg < 5; vg++)
                #pragma unroll
                for (int hh = 0; hh < 2; hh++)
                    mma16816(oacc[vg*2+hh], Pa_h, Vh4[vg][2*hh], Vh4[vg][2*hh+1]);
            #pragma unroll
            for (int vg = 0; vg < 5; vg++)
                #pragma unroll
                for (int hh = 0; hh < 2; hh++)
                    mma16816(oacc[vg*2+hh], Pa_l, Vh4[vg][2*hh], Vh4[vg][2*hh+1]);
            #pragma unroll
            for (int vg = 0; vg < 5; vg++)
                #pragma unroll
                for (int hh = 0; hh < 2; hh++)
                    mma16816(oacc[vg*2+hh], Pa_h, Vl4[vg][2*hh], Vl4[vg][2*hh+1]);
        }
    }

    // ---- finalize: normalize and write ch/cl ----
    const float inv0 = 1.f / l0, inv1 = 1.f / l1;
    const int s0 = qt*128 + w*16 + (lane >> 2);
    const int s1 = s0 + 8;
    #pragma unroll
    for (int nb = 0; nb < 10; nb++) {
        const int d = nb*8 + (lane & 3) * 2;
        {
            const size_t di = ((size_t)b * SQ + s0) * DM + h * HD + d;
            float o0 = oacc[nb][0] * inv0, o1 = oacc[nb][1] * inv0;
            __nv_bfloat16 h0 = __float2bfloat16_rn(o0);
            __nv_bfloat16 h1 = __float2bfloat16_rn(o1);
            *(__nv_bfloat162*)&ch_g[di] = __nv_bfloat162(h0, h1);
            *(__nv_bfloat162*)&cl_g[di] = __floats2bfloat162_rn(
                o0 - __bfloat162float(h0), o1 - __bfloat162float(h1));
        }
        {
            const size_t di = ((size_t)b * SQ + s1) * DM + h * HD + d;
            float o0 = oacc[nb][2] * inv1, o1 = oacc[nb][3] * inv1;
            __nv_bfloat16 h0 = __float2bfloat16_rn(o0);
            __nv_bfloat16 h1 = __float2bfloat16_rn(o1);
            *(__nv_bfloat162*)&ch_g[di] = __nv_bfloat162(h0, h1);
            *(__nv_bfloat162*)&cl_g[di] = __floats2bfloat162_rn(
                o0 - __bfloat162float(h0), o1 - __bfloat162float(h1));
        }
    }
}

// ---------------------------------------------------------------------------
extern "C" void kernel_launch(void* const* d_in, const int* in_sizes, int n_in,
                              void* d_out, int out_size)
{
    (void)in_sizes; (void)n_in; (void)out_size;
    const float* x     = (const float*)d_in[0];
    const float* cosp  = (const float*)d_in[1];
    const float* sinp  = (const float*)d_in[2];
    const float* Wqkv  = (const float*)d_in[3];
    const float* bqkv  = (const float*)d_in[4];
    const float* Wproj = (const float*)d_in[5];
    const float* bproj = (const float*)d_in[6];
    float* out = (float*)d_out;

    cudaFuncSetAttribute(gemm_bf16<true>,
                         cudaFuncAttributeMaxDynamicSharedMemorySize, GEMM_DSMEM);
    cudaFuncSetAttribute(gemm_bf16<false>,
                         cudaFuncAttributeMaxDynamicSharedMemorySize, GEMM_DSMEM);
    cudaFuncSetAttribute(attn_tc,
                         cudaFuncAttributeMaxDynamicSharedMemorySize, ATTN_SMEM);

    __nv_bfloat16 *xh, *xl, *wqh, *wql, *wph, *wpl, *ch, *cl;
    cudaGetSymbolAddress((void**)&xh,  xh_g);
    cudaGetSymbolAddress((void**)&xl,  xl_g);
    cudaGetSymbolAddress((void**)&wqh, wqh_g);
    cudaGetSymbolAddress((void**)&wql, wql_g);
    cudaGetSymbolAddress((void**)&wph, wph_g);
    cudaGetSymbolAddress((void**)&wpl, wpl_g);
    cudaGetSymbolAddress((void**)&ch,  ch_g);
    cudaGetSymbolAddress((void**)&cl,  cl_g);

    // 0) splits
    split_kernel<<<(MTOT*DM/4 + 255)/256, 256>>>(x, xh, xl, MTOT*DM/4);
    split_kernel<<<(NQKV*DM/4 + 255)/256, 256>>>(Wqkv, wqh, wql, NQKV*DM/4);
    split_kernel<<<(DM*DM/4 + 255)/256, 256>>>(Wproj, wph, wpl, DM*DM/4);
    // 1) QKV GEMM: q,k fp32 head-major + v bf16 hi/lo
    gemm_bf16<true><<<dim3(NQKV/128, MTOT/128), 256, GEMM_DSMEM>>>(
        xh, xl, wqh, wql, bqkv, nullptr);
    // 2) RoPE -> qh/ql, kh/kl
    rope_kernel<<<(NB*NH*SQ*40)/256, 256>>>(cosp, sinp);
    // 3) attention -> ch/cl
    attn_tc<<<dim3(SQ/128, NB*NH), 256, ATTN_SMEM>>>();
    // 4) output projection
    gemm_bf16<false><<<dim3(DM/128, MTOT/128), 256, GEMM_DSMEM>>>(
        ch, cl, wph, wpl, bproj, out);
}

// round 8
// speedup vs baseline: 1.1169x; 1.1169x over previous
#include <cuda_runtime.h>
#include <cuda_bf16.h>
#include <cstdint>

#define NB 4
#define SQ 1024
#define DM 1280
#define NH 16
#define HD 80
#define MTOT (NB*SQ)      // 4096
#define NQKV (3*DM)       // 3840

// ---------------------------------------------------------------------------
// Scratch (__device__ globals; allocation-free rule)
// ---------------------------------------------------------------------------
__device__ float g_q[NB*NH*SQ*HD];
__device__ float g_k[NB*NH*SQ*HD];

__device__ __nv_bfloat16 xh_g[MTOT*DM],  xl_g[MTOT*DM];
__device__ __nv_bfloat16 wqh_g[NQKV*DM], wql_g[NQKV*DM];
__device__ __nv_bfloat16 wph_g[DM*DM],   wpl_g[DM*DM];
__device__ __nv_bfloat16 qh_g[NB*NH*SQ*HD], ql_g[NB*NH*SQ*HD];
__device__ __nv_bfloat16 kh_g[NB*NH*SQ*HD], kl_g[NB*NH*SQ*HD];
__device__ __nv_bfloat16 vh_g[NB*NH*SQ*HD], vl_g[NB*NH*SQ*HD];
__device__ __nv_bfloat16 ch_g[MTOT*DM],  cl_g[MTOT*DM];

// ---------------------------------------------------------------------------
// helpers
// ---------------------------------------------------------------------------
__device__ __forceinline__ uint32_t s2u(const void* p) {
    uint32_t a;
    asm("{ .reg .u64 t; cvta.to.shared.u64 t, %1; cvt.u32.u64 %0, t; }"
        : "=r"(a) : "l"(p));
    return a;
}
__device__ __forceinline__ void ldm_x4(uint32_t* r, uint32_t addr) {
    asm volatile("ldmatrix.sync.aligned.m8n8.x4.shared.b16 {%0,%1,%2,%3}, [%4];"
        : "=r"(r[0]), "=r"(r[1]), "=r"(r[2]), "=r"(r[3]) : "r"(addr));
}
__device__ __forceinline__ void ldm_x4_t(uint32_t* r, uint32_t addr) {
    asm volatile("ldmatrix.sync.aligned.m8n8.x4.trans.shared.b16 {%0,%1,%2,%3}, [%4];"
        : "=r"(r[0]), "=r"(r[1]), "=r"(r[2]), "=r"(r[3]) : "r"(addr));
}
__device__ __forceinline__ void mma16816(float* c, const uint32_t* a,
                                         uint32_t b0, uint32_t b1) {
    asm volatile(
        "mma.sync.aligned.m16n8k16.row.col.f32.bf16.bf16.f32 "
        "{%0,%1,%2,%3}, {%4,%5,%6,%7}, {%8,%9}, {%0,%1,%2,%3};"
        : "+f"(c[0]), "+f"(c[1]), "+f"(c[2]), "+f"(c[3])
        : "r"(a[0]), "r"(a[1]), "r"(a[2]), "r"(a[3]), "r"(b0), "r"(b1));
}
__device__ __forceinline__ uint32_t packbf(float a, float b) {
    __nv_bfloat162 t = __floats2bfloat162_rn(a, b);
    return *reinterpret_cast<uint32_t*>(&t);
}
__device__ __forceinline__ void cpasync16(uint32_t dst, const void* src) {
    asm volatile("cp.async.ca.shared.global [%0], [%1], 16;"
        :: "r"(dst), "l"(src) : "memory");
}
#define CP_COMMIT() asm volatile("cp.async.commit_group;" ::: "memory")
#define CP_WAIT0()  asm volatile("cp.async.wait_group 0;" ::: "memory")
#define CP_WAIT1()  asm volatile("cp.async.wait_group 1;" ::: "memory")

// ---------------------------------------------------------------------------
// fp32 -> bf16 hi/lo split
// ---------------------------------------------------------------------------
__global__ void __launch_bounds__(256) split_kernel(
    const float* __restrict__ src, __nv_bfloat16* __restrict__ hi,
    __nv_bfloat16* __restrict__ lo, int n4)
{
    const int i = blockIdx.x * 256 + threadIdx.x;
    if (i >= n4) return;
    float4 v = ((const float4*)src)[i];
    __nv_bfloat16 h0 = __float2bfloat16_rn(v.x), h1 = __float2bfloat16_rn(v.y);
    __nv_bfloat16 h2 = __float2bfloat16_rn(v.z), h3 = __float2bfloat16_rn(v.w);
    ((__nv_bfloat162*)hi)[2*i+0] = __nv_bfloat162(h0, h1);
    ((__nv_bfloat162*)hi)[2*i+1] = __nv_bfloat162(h2, h3);
    ((__nv_bfloat162*)lo)[2*i+0] = __floats2bfloat162_rn(
        v.x - __bfloat162float(h0), v.y - __bfloat162float(h1));
    ((__nv_bfloat162*)lo)[2*i+1] = __floats2bfloat162_rn(
        v.z - __bfloat162float(h2), v.w - __bfloat162float(h3));
}

// ===========================================================================
// GEMM: C[m,n] = sum_k A[m,k]*W[n,k] + bias[n], pre-split bf16, mma.sync.
// Tile 128x128, K-stage 32, TWO-stage cp.async pipeline (80KB smem),
// 128 threads (4 warps, 64x64 warp tile), 2 CTAs/SM.
// ===========================================================================
#define KSTAGE 32
#define NIT (DM / KSTAGE)          // 40
#define PITCH 80
#define MAT_BYTES (128 * PITCH)    // 10240
#define STAGE_BYTES (4 * MAT_BYTES)
#define GEMM_DSMEM (2 * STAGE_BYTES)   // 81920

template<bool QKV>
__global__ void __launch_bounds__(128, 2) gemm_bf16(
    const __nv_bfloat16* __restrict__ Ah_g, const __nv_bfloat16* __restrict__ Al_g,
    const __nv_bfloat16* __restrict__ Bh_g, const __nv_bfloat16* __restrict__ Bl_g,
    const float* __restrict__ bias, float* __restrict__ Cout)
{
    extern __shared__ char dsm_raw[];
    const uint32_t base = s2u(dsm_raw);

    const int tid  = threadIdx.x;
    const int wid  = tid >> 5, lane = tid & 31;
    const int bx = blockIdx.x, by = blockIdx.y;
    const int wm = wid >> 1, wn = wid & 1;      // warp tile: 64(M) x 64(N)

    const __nv_bfloat16* bases[4] = {
        Ah_g + (size_t)(by * 128) * DM, Al_g + (size_t)(by * 128) * DM,
        Bh_g + (size_t)(bx * 128) * DM, Bl_g + (size_t)(bx * 128) * DM };

    auto ISSUE = [&](int it) {
        const uint32_t sb = base + (it & 1) * STAGE_BYTES;
        #pragma unroll
        for (int j = 0; j < 16; j++) {
            const int idx = tid + 128 * j;        // 0..2047
            const int mat = idx >> 9;
            const int rem = idx & 511;
            const int r = rem >> 2, c = rem & 3;
            const uint32_t dst = sb + mat * MAT_BYTES + r * PITCH + c * 16;
            const __nv_bfloat16* src = bases[mat] + (size_t)r * DM + it * KSTAGE + c * 8;
            cpasync16(dst, src);
        }
        CP_COMMIT();
    };

    float acc[4][8][4];
    #pragma unroll
    for (int i = 0; i < 4; i++)
        #pragma unroll
        for (int j = 0; j < 8; j++)
            #pragma unroll
            for (int q = 0; q < 4; q++) acc[i][j][q] = 0.f;

    ISSUE(0); ISSUE(1);

    for (int it = 0; it < NIT; ++it) {
        if (it == NIT - 1) { CP_WAIT0(); } else { CP_WAIT1(); }
        __syncthreads();

        const uint32_t sb = base + (it & 1) * STAGE_BYTES;
        #pragma unroll
        for (int kc = 0; kc < 2; kc++) {
            uint32_t Ah[4][4], Al[4][4];
            #pragma unroll
            for (int mf = 0; mf < 4; mf++) {
                const uint32_t aoff =
                    (uint32_t)((wm*64 + mf*16 + (lane & 15)) * PITCH
                               + kc*32 + (lane >> 4) * 16);
                ldm_x4(Ah[mf], sb + aoff);
                ldm_x4(Al[mf], sb + MAT_BYTES + aoff);
            }
            uint32_t Bh[4][4], Bl[4][4];
            #pragma unroll
            for (int g = 0; g < 4; g++) {
                const int quad = lane >> 3;
                const uint32_t boff =
                    (uint32_t)((wn*64 + g*16 + (quad >> 1) * 8 + (lane & 7)) * PITCH
                               + kc*32 + (quad & 1) * 16);
                ldm_x4(Bh[g], sb + 2*MAT_BYTES + boff);
                ldm_x4(Bl[g], sb + 3*MAT_BYTES + boff);
            }
            #pragma unroll
            for (int mf = 0; mf < 4; mf++)
                #pragma unroll
                for (int nb = 0; nb < 8; nb++)
                    mma16816(acc[mf][nb], Ah[mf], Bh[nb>>1][(nb&1)*2], Bh[nb>>1][(nb&1)*2+1]);
            #pragma unroll
            for (int mf = 0; mf < 4; mf++)
                #pragma unroll
                for (int nb = 0; nb < 8; nb++)
                    mma16816(acc[mf][nb], Al[mf], Bh[nb>>1][(nb&1)*2], Bh[nb>>1][(nb&1)*2+1]);
            #pragma unroll
            for (int mf = 0; mf < 4; mf++)
                #pragma unroll
                for (int nb = 0; nb < 8; nb++)
                    mma16816(acc[mf][nb], Ah[mf], Bl[nb>>1][(nb&1)*2], Bl[nb>>1][(nb&1)*2+1]);
        }
        __syncthreads();
        if (it + 2 < NIT) ISSUE(it + 2);
    }

    // Epilogue
    #pragma unroll
    for (int mf = 0; mf < 4; mf++)
        #pragma unroll
        for (int nb = 0; nb < 8; nb++)
            #pragma unroll
            for (int ci = 0; ci < 2; ci++) {
                const int m = by*128 + wm*64 + mf*16 + (lane >> 2) + ci*8;
                const int n = bx*128 + wn*64 + nb*8 + (lane & 3) * 2;
                float2 v;
                v.x = acc[mf][nb][2*ci+0] + bias[n];
                v.y = acc[mf][nb][2*ci+1] + bias[n+1];
                if (QKV) {
                    const int sel = n / DM;
                    const int r2  = n - sel * DM;
                    const int h   = r2 / HD;
                    const int dd  = r2 - h * HD;
                    const int bb  = m >> 10;
                    const int ss  = m & (SQ - 1);
                    const size_t di = (((size_t)bb * NH + h) * SQ + ss) * HD + dd;
                    if (sel == 0)      *(float2*)&g_q[di] = v;
                    else if (sel == 1) *(float2*)&g_k[di] = v;
                    else {
                        __nv_bfloat16 h0 = __float2bfloat16_rn(v.x);
                        __nv_bfloat16 h1 = __float2bfloat16_rn(v.y);
                        *(__nv_bfloat162*)&vh_g[di] = __nv_bfloat162(h0, h1);
                        *(__nv_bfloat162*)&vl_g[di] = __floats2bfloat162_rn(
                            v.x - __bfloat162float(h0), v.y - __bfloat162float(h1));
                    }
                } else {
                    *(float2*)&Cout[(size_t)m * DM + n] = v;
                }
            }
}

// ---------------------------------------------------------------------------
// RoPE: read g_q/g_k fp32, write rotated bf16 hi/lo
// ---------------------------------------------------------------------------
__global__ void __launch_bounds__(256) rope_kernel(
    const float* __restrict__ cosp, const float* __restrict__ sinp)
{
    const int idx  = blockIdx.x * 256 + threadIdx.x;   // < NB*NH*SQ*40
    const int d    = idx % 40;
    const int rest = idx / 40;
    const int ss   = rest & (SQ - 1);
    const int bh   = rest >> 10;
    const size_t base = ((size_t)bh * SQ + ss) * HD;
    const float c1 = cosp[ss*HD + d],      s1 = sinp[ss*HD + d];
    const float c2 = cosp[ss*HD + d + 40], s2 = sinp[ss*HD + d + 40];

    float q1 = g_q[base + d], q2 = g_q[base + d + 40];
    float o1 = q1*c1 - q2*s1;
    float o2 = q2*c2 + q1*s2;
    __nv_bfloat16 h;
    h = __float2bfloat16_rn(o1); qh_g[base+d]    = h; ql_g[base+d]    = __float2bfloat16_rn(o1 - __bfloat162float(h));
    h = __float2bfloat16_rn(o2); qh_g[base+d+40] = h; ql_g[base+d+40] = __float2bfloat16_rn(o2 - __bfloat162float(h));

    float k1 = g_k[base + d], k2 = g_k[base + d + 40];
    o1 = k1*c1 - k2*s1;
    o2 = k2*c2 + k1*s2;
    h = __float2bfloat16_rn(o1); kh_g[base+d]    = h; kl_g[base+d]    = __float2bfloat16_rn(o1 - __bfloat162float(h));
    h = __float2bfloat16_rn(o2); kh_g[base+d+40] = h; kl_g[base+d+40] = __float2bfloat16_rn(o2 - __bfloat162float(h));
}

// ===========================================================================
// Flash attention on mma.sync. CTA = (q-tile 128 rows, bh), 8 warps (256 thr).
// Double-buffered K/V via cp.async; fragment softmax; bf16 hi/lo output.
// (Exact round-6 structure.)
// ===========================================================================
#define APITCH 176                        // bytes per 80-elem bf16 row (+pad)
#define AMATQ (128*APITCH)                // 22528 per Q matrix (128 rows)
#define AMAT64 (64*APITCH)                // 11264 per KV matrix (64 rows)
#define AQH 0
#define AQL AMATQ
#define AKV0 (2*AMATQ)                    // 45056
#define KV_STAGE (4*AMAT64)               // 45056
#define ATTN_SMEM (2*AMATQ + 2*KV_STAGE)  // 135168

__global__ void __launch_bounds__(256) attn_tc()
{
    extern __shared__ char dsm_raw[];
    const uint32_t base = s2u(dsm_raw);

    const int tid = threadIdx.x;
    const int w = tid >> 5, lane = tid & 31;
    const int qt = blockIdx.x, bh = blockIdx.y;
    const int b = bh >> 4, h = bh & 15;
    const float scale = 0.11180339887498948f;  // 1/sqrt(80)

    const size_t krow0base = (size_t)bh * SQ;

    auto ISSUE_KV = [&](int kt) {
        const uint32_t sb = base + AKV0 + (kt & 1) * KV_STAGE;
        const size_t krow0 = krow0base + kt * 64;
        const __nv_bfloat16* srcs[4] = { kh_g, kl_g, vh_g, vl_g };
        #pragma unroll
        for (int j = 0; j < 10; j++) {
            const int idx = tid + 256 * j;   // 0..2559
            const int mat = idx / 640;
            const int rem = idx - mat * 640;
            const int r = rem / 10, c = rem - r * 10;
            cpasync16(sb + mat * AMAT64 + r * APITCH + c * 16,
                      srcs[mat] + (krow0 + r) * HD + c * 8);
        }
        CP_COMMIT();
    };

    // Q tile load (once): 128 rows x 10 chunks x 2 matrices = 2560
    {
        const size_t qrow0 = krow0base + qt * 128;
        #pragma unroll
        for (int j = 0; j < 10; j++) {
            const int idx = tid + 256 * j;
            const int mat = idx / 1280;
            const int rem = idx - mat * 1280;
            const int r = rem / 10, c = rem - r * 10;
            cpasync16(base + (mat ? AQL : AQH) + r * APITCH + c * 16,
                      (mat ? ql_g : qh_g) + (qrow0 + r) * HD + c * 8);
        }
        CP_COMMIT();
    }
    ISSUE_KV(0);

    float oacc[10][4];
    #pragma unroll
    for (int i = 0; i < 10; i++)
        #pragma unroll
        for (int j = 0; j < 4; j++) oacc[i][j] = 0.f;
    float m0 = -1e30f, m1 = -1e30f, l0 = 0.f, l1 = 0.f;

    for (int kt = 0; kt < 16; kt++) {
        if (kt + 1 < 16) { ISSUE_KV(kt + 1); CP_WAIT1(); } else { CP_WAIT0(); }
        __syncthreads();

        const uint32_t kvb = base + AKV0 + (kt & 1) * KV_STAGE;
        const uint32_t sKH = kvb, sKL = kvb + AMAT64;
        const uint32_t sVH = kvb + 2*AMAT64, sVL = kvb + 3*AMAT64;

        // ---- S = Q K^T (16x64 per warp), 3-pass split ----
        float sacc[8][4];
        #pragma unroll
        for (int i = 0; i < 8; i++)
            #pragma unroll
            for (int j = 0; j < 4; j++) sacc[i][j] = 0.f;

        #pragma unroll
        for (int kc = 0; kc < 5; kc++) {
            uint32_t Aah[4], Aal[4];
            const uint32_t aoff =
                (uint32_t)((w*16 + (lane & 15)) * APITCH + kc*32 + (lane >> 4) * 16);
            ldm_x4(Aah, base + AQH + aoff);
            ldm_x4(Aal, base + AQL + aoff);
            uint32_t Bh4[4][4], Bl4[4][4];
            #pragma unroll
            for (int g = 0; g < 4; g++) {
                const int quad = lane >> 3;
                const uint32_t boff =
                    (uint32_t)((g*16 + (quad >> 1) * 8 + (lane & 7)) * APITCH
                               + kc*32 + (quad & 1) * 16);
                ldm_x4(Bh4[g], sKH + boff);
                ldm_x4(Bl4[g], sKL + boff);
            }
            #pragma unroll
            for (int g = 0; g < 4; g++)
                #pragma unroll
                for (int hh = 0; hh < 2; hh++)
                    mma16816(sacc[g*2+hh], Aah, Bh4[g][2*hh], Bh4[g][2*hh+1]);
            #pragma unroll
            for (int g = 0; g < 4; g++)
                #pragma unroll
                for (int hh = 0; hh < 2; hh++)
                    mma16816(sacc[g*2+hh], Aal, Bh4[g][2*hh], Bh4[g][2*hh+1]);
            #pragma unroll
            for (int g = 0; g < 4; g++)
                #pragma unroll
                for (int hh = 0; hh < 2; hh++)
                    mma16816(sacc[g*2+hh], Aah, Bl4[g][2*hh], Bl4[g][2*hh+1]);
        }

        // ---- online softmax on fragments ----
        #pragma unroll
        for (int nb = 0; nb < 8; nb++)
            #pragma unroll
            for (int j = 0; j < 4; j++) sacc[nb][j] *= scale;

        float mx0 = -1e30f, mx1 = -1e30f;
        #pragma unroll
        for (int nb = 0; nb < 8; nb++) {
            mx0 = fmaxf(mx0, fmaxf(sacc[nb][0], sacc[nb][1]));
            mx1 = fmaxf(mx1, fmaxf(sacc[nb][2], sacc[nb][3]));
        }
        mx0 = fmaxf(mx0, __shfl_xor_sync(0xffffffffu, mx0, 1));
        mx0 = fmaxf(mx0, __shfl_xor_sync(0xffffffffu, mx0, 2));
        mx1 = fmaxf(mx1, __shfl_xor_sync(0xffffffffu, mx1, 1));
        mx1 = fmaxf(mx1, __shfl_xor_sync(0xffffffffu, mx1, 2));

        const float mn0 = fmaxf(m0, mx0), mn1 = fmaxf(m1, mx1);
        const float al0 = __expf(m0 - mn0), al1 = __expf(m1 - mn1);
        m0 = mn0; m1 = mn1;

        float rs0 = 0.f, rs1 = 0.f;
        #pragma unroll
        for (int nb = 0; nb < 8; nb++) {
            sacc[nb][0] = __expf(sacc[nb][0] - m0);
            sacc[nb][1] = __expf(sacc[nb][1] - m0);
            sacc[nb][2] = __expf(sacc[nb][2] - m1);
            sacc[nb][3] = __expf(sacc[nb][3] - m1);
            rs0 += sacc[nb][0] + sacc[nb][1];
            rs1 += sacc[nb][2] + sacc[nb][3];
        }
        rs0 += __shfl_xor_sync(0xffffffffu, rs0, 1);
        rs0 += __shfl_xor_sync(0xffffffffu, rs0, 2);
        rs1 += __shfl_xor_sync(0xffffffffu, rs1, 1);
        rs1 += __shfl_xor_sync(0xffffffffu, rs1, 2);
        l0 = l0 * al0 + rs0;
        l1 = l1 * al1 + rs1;

        #pragma unroll
        for (int nb = 0; nb < 10; nb++) {
            oacc[nb][0] *= al0; oacc[nb][1] *= al0;
            oacc[nb][2] *= al1; oacc[nb][3] *= al1;
        }

        // ---- O += P @ V, 3-pass ----
        #pragma unroll
        for (int kc = 0; kc < 4; kc++) {
            uint32_t Pa_h[4], Pa_l[4];
            #pragma unroll
            for (int half2i = 0; half2i < 2; half2i++) {
                const int nb = 2*kc + half2i;
                float f0 = sacc[nb][0], f1 = sacc[nb][1];
                float f2 = sacc[nb][2], f3 = sacc[nb][3];
                float h0 = __bfloat162float(__float2bfloat16_rn(f0));
                float h1 = __bfloat162float(__float2bfloat16_rn(f1));
                float h2 = __bfloat162float(__float2bfloat16_rn(f2));
                float h3 = __bfloat162float(__float2bfloat16_rn(f3));
                Pa_h[2*half2i+0] = packbf(h0, h1);
                Pa_h[2*half2i+1] = packbf(h2, h3);
                Pa_l[2*half2i+0] = packbf(f0 - h0, f1 - h1);
                Pa_l[2*half2i+1] = packbf(f2 - h2, f3 - h3);
            }
            uint32_t Vh4[5][4], Vl4[5][4];
            #pragma unroll
            for (int vg = 0; vg < 5; vg++) {
                const int vrow = kc*16 + ((lane >> 3) & 1) * 8 + (lane & 7);
                const int vcol = vg*16 + (lane >> 4) * 8;
                const uint32_t voff = (uint32_t)(vrow * APITCH + vcol * 2);
                ldm_x4_t(Vh4[vg], sVH + voff);
                ldm_x4_t(Vl4[vg], sVL + voff);
            }
            #pragma unroll
            for (int vg = 0; vg < 5; vg++)
                #pragma unroll
                for (int hh = 0; hh < 2; hh++)
                    mma16816(oacc[vg*2+hh], Pa_h, Vh4[vg][2*hh], Vh4[vg][2*hh+1]);
            #pragma unroll
            for (int vg = 0; vg < 5; vg++)
                #pragma unroll
                for (int hh = 0; hh < 2; hh++)
                    mma16816(oacc[vg*2+hh], Pa_l, Vh4[vg][2*hh], Vh4[vg][2*hh+1]);
            #pragma unroll
            for (int vg = 0; vg < 5; vg++)
                #pragma unroll
                for (int hh = 0; hh < 2; hh++)
                    mma16816(oacc[vg*2+hh], Pa_h, Vl4[vg][2*hh], Vl4[vg][2*hh+1]);
        }
        __syncthreads();
    }

    // ---- finalize: normalize and write ch/cl ----
    const float inv0 = 1.f / l0, inv1 = 1.f / l1;
    const int s0 = qt*128 + w*16 + (lane >> 2);
    const int s1 = s0 + 8;
    #pragma unroll
    for (int nb = 0; nb < 10; nb++) {
        const int d = nb*8 + (lane & 3) * 2;
        {
            const size_t di = ((size_t)b * SQ + s0) * DM + h * HD + d;
            float o0 = oacc[nb][0] * inv0, o1 = oacc[nb][1] * inv0;
            __nv_bfloat16 h0 = __float2bfloat16_rn(o0);
            __nv_bfloat16 h1 = __float2bfloat16_rn(o1);
            *(__nv_bfloat162*)&ch_g[di] = __nv_bfloat162(h0, h1);
            *(__nv_bfloat162*)&cl_g[di] = __floats2bfloat162_rn(
                o0 - __bfloat162float(h0), o1 - __bfloat162float(h1));
        }
        {
            const size_t di = ((size_t)b * SQ + s1) * DM + h * HD + d;
            float o0 = oacc[nb][2] * inv1, o1 = oacc[nb][3] * inv1;
            __nv_bfloat16 h0 = __float2bfloat16_rn(o0);
            __nv_bfloat16 h1 = __float2bfloat16_rn(o1);
            *(__nv_bfloat162*)&ch_g[di] = __nv_bfloat162(h0, h1);
            *(__nv_bfloat162*)&cl_g[di] = __floats2bfloat162_rn(
                o0 - __bfloat162float(h0), o1 - __bfloat162float(h1));
        }
    }
}

// ---------------------------------------------------------------------------
extern "C" void kernel_launch(void* const* d_in, const int* in_sizes, int n_in,
                              void* d_out, int out_size)
{
    (void)in_sizes; (void)n_in; (void)out_size;
    const float* x     = (const float*)d_in[0];
    const float* cosp  = (const float*)d_in[1];
    const float* sinp  = (const float*)d_in[2];
    const float* Wqkv  = (const float*)d_in[3];
    const float* bqkv  = (const float*)d_in[4];
    const float* Wproj = (const float*)d_in[5];
    const float* bproj = (const float*)d_in[6];
    float* out = (float*)d_out;

    cudaFuncSetAttribute(gemm_bf16<true>,
                         cudaFuncAttributeMaxDynamicSharedMemorySize, GEMM_DSMEM);
    cudaFuncSetAttribute(gemm_bf16<false>,
                         cudaFuncAttributeMaxDynamicSharedMemorySize, GEMM_DSMEM);
    cudaFuncSetAttribute(attn_tc,
                         cudaFuncAttributeMaxDynamicSharedMemorySize, ATTN_SMEM);

    __nv_bfloat16 *xh, *xl, *wqh, *wql, *wph, *wpl, *ch, *cl;
    cudaGetSymbolAddress((void**)&xh,  xh_g);
    cudaGetSymbolAddress((void**)&xl,  xl_g);
    cudaGetSymbolAddress((void**)&wqh, wqh_g);
    cudaGetSymbolAddress((void**)&wql, wql_g);
    cudaGetSymbolAddress((void**)&wph, wph_g);
    cudaGetSymbolAddress((void**)&wpl, wpl_g);
    cudaGetSymbolAddress((void**)&ch,  ch_g);
    cudaGetSymbolAddress((void**)&cl,  cl_g);

    // 0) splits
    split_kernel<<<(MTOT*DM/4 + 255)/256, 256>>>(x, xh, xl, MTOT*DM/4);
    split_kernel<<<(NQKV*DM/4 + 255)/256, 256>>>(Wqkv, wqh, wql, NQKV*DM/4);
    split_kernel<<<(DM*DM/4 + 255)/256, 256>>>(Wproj, wph, wpl, DM*DM/4);
    // 1) QKV GEMM: q,k fp32 head-major + v bf16 hi/lo
    gemm_bf16<true><<<dim3(NQKV/128, MTOT/128), 128, GEMM_DSMEM>>>(
        xh, xl, wqh, wql, bqkv, nullptr);
    // 2) RoPE -> qh/ql, kh/kl
    rope_kernel<<<(NB*NH*SQ*40)/256, 256>>>(cosp, sinp);
    // 3) attention -> ch/cl
    attn_tc<<<dim3(SQ/128, NB*NH), 256, ATTN_SMEM>>>();
    // 4) output projection
    gemm_bf16<false><<<dim3(DM/128, MTOT/128), 128, GEMM_DSMEM>>>(
        ch, cl, wph, wpl, bproj, out);
}

// round 9
// speedup vs baseline: 1.4639x; 1.3107x over previous
#include <cuda_runtime.h>
#include <cuda_bf16.h>
#include <cstdint>

#define NB 4
#define SQ 1024
#define DM 1280
#define NH 16
#define HD 80
#define MTOT (NB*SQ)      // 4096
#define NQKV (3*DM)       // 3840

// ---------------------------------------------------------------------------
// Scratch (__device__ globals; allocation-free rule)
// ---------------------------------------------------------------------------
__device__ float g_q[NB*NH*SQ*HD];
__device__ float g_k[NB*NH*SQ*HD];

// int8 2-digit operands for QKV GEMM
__device__ int8_t xq1_g[MTOT*DM],  xq2_g[MTOT*DM];
__device__ int8_t wq1_g[NQKV*DM],  wq2_g[NQKV*DM];
__device__ float  sax_g[MTOT];      // row scales for x
__device__ float  sbw_g[NQKV];      // row scales for Wqkv

// bf16 hi/lo for proj GEMM + attention
__device__ __nv_bfloat16 wph_g[DM*DM],   wpl_g[DM*DM];
__device__ __nv_bfloat16 qh_g[NB*NH*SQ*HD], ql_g[NB*NH*SQ*HD];
__device__ __nv_bfloat16 kh_g[NB*NH*SQ*HD], kl_g[NB*NH*SQ*HD];
__device__ __nv_bfloat16 vh_g[NB*NH*SQ*HD], vl_g[NB*NH*SQ*HD];
__device__ __nv_bfloat16 ch_g[MTOT*DM],  cl_g[MTOT*DM];

// ---------------------------------------------------------------------------
// helpers
// ---------------------------------------------------------------------------
__device__ __forceinline__ uint32_t s2u(const void* p) {
    uint32_t a;
    asm("{ .reg .u64 t; cvta.to.shared.u64 t, %1; cvt.u32.u64 %0, t; }"
        : "=r"(a) : "l"(p));
    return a;
}
__device__ __forceinline__ void ldm_x4(uint32_t* r, uint32_t addr) {
    asm volatile("ldmatrix.sync.aligned.m8n8.x4.shared.b16 {%0,%1,%2,%3}, [%4];"
        : "=r"(r[0]), "=r"(r[1]), "=r"(r[2]), "=r"(r[3]) : "r"(addr));
}
__device__ __forceinline__ void ldm_x4_t(uint32_t* r, uint32_t addr) {
    asm volatile("ldmatrix.sync.aligned.m8n8.x4.trans.shared.b16 {%0,%1,%2,%3}, [%4];"
        : "=r"(r[0]), "=r"(r[1]), "=r"(r[2]), "=r"(r[3]) : "r"(addr));
}
__device__ __forceinline__ void mma16816(float* c, const uint32_t* a,
                                         uint32_t b0, uint32_t b1) {
    asm volatile(
        "mma.sync.aligned.m16n8k16.row.col.f32.bf16.bf16.f32 "
        "{%0,%1,%2,%3}, {%4,%5,%6,%7}, {%8,%9}, {%0,%1,%2,%3};"
        : "+f"(c[0]), "+f"(c[1]), "+f"(c[2]), "+f"(c[3])
        : "r"(a[0]), "r"(a[1]), "r"(a[2]), "r"(a[3]), "r"(b0), "r"(b1));
}
__device__ __forceinline__ void mma_s8(int* c, const uint32_t* a,
                                       uint32_t b0, uint32_t b1) {
    asm volatile(
        "mma.sync.aligned.m16n8k32.row.col.s32.s8.s8.s32 "
        "{%0,%1,%2,%3}, {%4,%5,%6,%7}, {%8,%9}, {%0,%1,%2,%3};"
        : "+r"(c[0]), "+r"(c[1]), "+r"(c[2]), "+r"(c[3])
        : "r"(a[0]), "r"(a[1]), "r"(a[2]), "r"(a[3]), "r"(b0), "r"(b1));
}
__device__ __forceinline__ uint32_t packbf(float a, float b) {
    __nv_bfloat162 t = __floats2bfloat162_rn(a, b);
    return *reinterpret_cast<uint32_t*>(&t);
}
__device__ __forceinline__ void cpasync16(uint32_t dst, const void* src) {
    asm volatile("cp.async.ca.shared.global [%0], [%1], 16;"
        :: "r"(dst), "l"(src) : "memory");
}
#define CP_COMMIT() asm volatile("cp.async.commit_group;" ::: "memory")
#define CP_WAIT0()  asm volatile("cp.async.wait_group 0;" ::: "memory")
#define CP_WAIT1()  asm volatile("cp.async.wait_group 1;" ::: "memory")

// ---------------------------------------------------------------------------
// fp32 -> bf16 hi/lo split (used for Wproj)
// ---------------------------------------------------------------------------
__global__ void __launch_bounds__(256) split_kernel(
    const float* __restrict__ src, __nv_bfloat16* __restrict__ hi,
    __nv_bfloat16* __restrict__ lo, int n4)
{
    const int i = blockIdx.x * 256 + threadIdx.x;
    if (i >= n4) return;
    float4 v = ((const float4*)src)[i];
    __nv_bfloat16 h0 = __float2bfloat16_rn(v.x), h1 = __float2bfloat16_rn(v.y);
    __nv_bfloat16 h2 = __float2bfloat16_rn(v.z), h3 = __float2bfloat16_rn(v.w);
    ((__nv_bfloat162*)hi)[2*i+0] = __nv_bfloat162(h0, h1);
    ((__nv_bfloat162*)hi)[2*i+1] = __nv_bfloat162(h2, h3);
    ((__nv_bfloat162*)lo)[2*i+0] = __floats2bfloat162_rn(
        v.x - __bfloat162float(h0), v.y - __bfloat162float(h1));
    ((__nv_bfloat162*)lo)[2*i+1] = __floats2bfloat162_rn(
        v.z - __bfloat162float(h2), v.w - __bfloat162float(h3));
}

// ---------------------------------------------------------------------------
// fp32 -> int8 2-digit quantization. One block (128 thr) per row of DM cols.
// x = s*(d1 + d2/250), s = rowmax/120.
// ---------------------------------------------------------------------------
__global__ void __launch_bounds__(128) quant_kernel(
    const float* __restrict__ src, int8_t* __restrict__ d1,
    int8_t* __restrict__ d2, float* __restrict__ scale)
{
    const int row = blockIdx.x;
    const int tid = threadIdx.x;
    const float* p = src + (size_t)row * DM;
    float mx = 0.f;
    for (int i = tid; i < DM; i += 128) mx = fmaxf(mx, fabsf(p[i]));
    #pragma unroll
    for (int off = 16; off >= 1; off >>= 1)
        mx = fmaxf(mx, __shfl_xor_sync(0xffffffffu, mx, off));
    __shared__ float smx[4];
    if ((tid & 31) == 0) smx[tid >> 5] = mx;
    __syncthreads();
    mx = fmaxf(fmaxf(smx[0], smx[1]), fmaxf(smx[2], smx[3]));
    const float s = (mx > 0.f) ? mx * (1.f / 120.f) : 1.f;
    const float inv = 1.f / s;
    for (int i = tid; i < DM; i += 128) {
        const float f  = p[i] * inv;
        const float q1 = rintf(f);
        const float q2 = rintf(250.f * (f - q1));
        d1[(size_t)row * DM + i] = (int8_t)(int)q1;
        d2[(size_t)row * DM + i] = (int8_t)(int)q2;
    }
    if (tid == 0) scale[row] = s;
}

// ===========================================================================
// QKV GEMM, int8 2-digit: C = sa[m]*sb[n]*(P11 + Pcross/250) + bias[n].
// CTA tile 128(M)x64(N), 256 thr, 8 warps of 32x32. K-stage 128 int8,
// 2-stage cp.async pipeline (110.6KB smem), 2 CTAs/SM.
// Epilogue scatters q,k fp32 head-major and v bf16 hi/lo.
// ===========================================================================
#define IK 128
#define NITI (DM / IK)             // 10
#define IPITCH 144                 // 128B data + 16B pad (conflict-free)
#define IOFF_A2 (128*IPITCH)       // 18432
#define IOFF_B1 (2*128*IPITCH)     // 36864
#define IOFF_B2 (IOFF_B1 + 64*IPITCH)  // 46080
#define ISTAGE (IOFF_B2 + 64*IPITCH)   // 55296
#define IGEMM_DSMEM (2*ISTAGE)         // 110592

__global__ void __launch_bounds__(256, 2) gemm_qkv_i8(
    const float* __restrict__ bias)
{
    extern __shared__ char dsm_raw[];
    const uint32_t base = s2u(dsm_raw);

    const int tid  = threadIdx.x;
    const int wid  = tid >> 5, lane = tid & 31;
    const int bx = blockIdx.x, by = blockIdx.y;
    const int wm = wid >> 1, wn = wid & 1;    // warp tile 32(M) x 32(N)

    const int8_t* a1p = xq1_g + (size_t)(by * 128) * DM;
    const int8_t* a2p = xq2_g + (size_t)(by * 128) * DM;
    const int8_t* b1p = wq1_g + (size_t)(bx * 64) * DM;
    const int8_t* b2p = wq2_g + (size_t)(bx * 64) * DM;

    auto ISSUE = [&](int it) {
        const uint32_t sb = base + (it & 1) * ISTAGE;
        const int kof = it * IK;
        #pragma unroll
        for (int j = 0; j < 12; j++) {
            const int idx = tid + 256 * j;
            int local; uint32_t moff; const int8_t* srcp;
            if (j < 4)       { local = idx;        moff = 0;       srcp = a1p; }
            else if (j < 8)  { local = idx - 1024; moff = IOFF_A2; srcp = a2p; }
            else if (j < 10) { local = idx - 2048; moff = IOFF_B1; srcp = b1p; }
            else             { local = idx - 2560; moff = IOFF_B2; srcp = b2p; }
            const int r = local >> 3, c = local & 7;
            cpasync16(sb + moff + r * IPITCH + c * 16,
                      srcp + (size_t)r * DM + kof + c * 16);
        }
        CP_COMMIT();
    };

    int accP[2][4][4], accX[2][4][4];
    #pragma unroll
    for (int i = 0; i < 2; i++)
        #pragma unroll
        for (int j = 0; j < 4; j++)
            #pragma unroll
            for (int q = 0; q < 4; q++) { accP[i][j][q] = 0; accX[i][j][q] = 0; }

    ISSUE(0); ISSUE(1);

    for (int it = 0; it < NITI; ++it) {
        if (it == NITI - 1) { CP_WAIT0(); } else { CP_WAIT1(); }
        __syncthreads();

        const uint32_t sb = base + (it & 1) * ISTAGE;
        #pragma unroll
        for (int kc = 0; kc < 4; kc++) {
            uint32_t Ad1[2][4], Ad2[2][4];
            #pragma unroll
            for (int mf = 0; mf < 2; mf++) {
                const uint32_t aoff =
                    (uint32_t)((wm*32 + mf*16 + (lane & 15)) * IPITCH
                               + kc*32 + (lane >> 4) * 16);
                ldm_x4(Ad1[mf], sb + aoff);
                ldm_x4(Ad2[mf], sb + IOFF_A2 + aoff);
            }
            uint32_t Bd1[2][4], Bd2[2][4];
            #pragma unroll
            for (int g = 0; g < 2; g++) {
                const int quad = lane >> 3;
                const uint32_t boff =
                    (uint32_t)((wn*32 + g*16 + (quad >> 1) * 8 + (lane & 7)) * IPITCH
                               + kc*32 + (quad & 1) * 16);
                ldm_x4(Bd1[g], sb + IOFF_B1 + boff);
                ldm_x4(Bd2[g], sb + IOFF_B2 + boff);
            }
            // pass 1: d1*e1 -> P
            #pragma unroll
            for (int mf = 0; mf < 2; mf++)
                #pragma unroll
                for (int nb = 0; nb < 4; nb++)
                    mma_s8(accP[mf][nb], Ad1[mf], Bd1[nb>>1][(nb&1)*2], Bd1[nb>>1][(nb&1)*2+1]);
            // pass 2: d1*e2 -> X
            #pragma unroll
            for (int mf = 0; mf < 2; mf++)
                #pragma unroll
                for (int nb = 0; nb < 4; nb++)
                    mma_s8(accX[mf][nb], Ad1[mf], Bd2[nb>>1][(nb&1)*2], Bd2[nb>>1][(nb&1)*2+1]);
            // pass 3: d2*e1 -> X
            #pragma unroll
            for (int mf = 0; mf < 2; mf++)
                #pragma unroll
                for (int nb = 0; nb < 4; nb++)
                    mma_s8(accX[mf][nb], Ad2[mf], Bd1[nb>>1][(nb&1)*2], Bd1[nb>>1][(nb&1)*2+1]);
        }
        __syncthreads();
        if (it + 2 < NITI) ISSUE(it + 2);
    }

    // Epilogue: reconstruct, bias, scatter
    #pragma unroll
    for (int mf = 0; mf < 2; mf++)
        #pragma unroll
        for (int nb = 0; nb < 4; nb++)
            #pragma unroll
            for (int ci = 0; ci < 2; ci++) {
                const int m = by*128 + wm*32 + mf*16 + (lane >> 2) + ci*8;
                const int n = bx*64 + wn*32 + nb*8 + (lane & 3) * 2;
                const float sa = sax_g[m];
                float2 v;
                v.x = sa * sbw_g[n]   * ((float)accP[mf][nb][2*ci+0]
                        + (float)accX[mf][nb][2*ci+0] * 0.004f) + bias[n];
                v.y = sa * sbw_g[n+1] * ((float)accP[mf][nb][2*ci+1]
                        + (float)accX[mf][nb][2*ci+1] * 0.004f) + bias[n+1];
                const int sel = n / DM;
                const int r2  = n - sel * DM;
                const int h   = r2 / HD;
                const int dd  = r2 - h * HD;
                const int bb  = m >> 10;
                const int ss  = m & (SQ - 1);
                const size_t di = (((size_t)bb * NH + h) * SQ + ss) * HD + dd;
                if (sel == 0)      *(float2*)&g_q[di] = v;
                else if (sel == 1) *(float2*)&g_k[di] = v;
                else {
                    __nv_bfloat16 h0 = __float2bfloat16_rn(v.x);
                    __nv_bfloat16 h1 = __float2bfloat16_rn(v.y);
                    *(__nv_bfloat162*)&vh_g[di] = __nv_bfloat162(h0, h1);
                    *(__nv_bfloat162*)&vl_g[di] = __floats2bfloat162_rn(
                        v.x - __bfloat162float(h0), v.y - __bfloat162float(h1));
                }
            }
}

// ===========================================================================
// Proj GEMM (round-6 bf16 3-pass version): out = ctx @ Wproj^T + bias
// ===========================================================================
#define KSTAGE 32
#define NIT (DM / KSTAGE)          // 40
#define PITCH 80
#define MAT_BYTES (128 * PITCH)    // 10240
#define STAGE_BYTES (4 * MAT_BYTES)
#define GEMM_DSMEM (2 * STAGE_BYTES)   // 81920

__global__ void __launch_bounds__(256, 2) gemm_proj(
    const float* __restrict__ bias, float* __restrict__ Cout)
{
    extern __shared__ char dsm_raw[];
    const uint32_t base = s2u(dsm_raw);

    const int tid  = threadIdx.x;
    const int wid  = tid >> 5, lane = tid & 31;
    const int bx = blockIdx.x, by = blockIdx.y;
    const int wm = wid >> 1, wn = wid & 1;      // warp tile: 32(M) x 64(N)

    const __nv_bfloat16* bases[4] = {
        ch_g + (size_t)(by * 128) * DM, cl_g + (size_t)(by * 128) * DM,
        wph_g + (size_t)(bx * 128) * DM, wpl_g + (size_t)(bx * 128) * DM };

    auto ISSUE = [&](int it) {
        const uint32_t sb = base + (it & 1) * STAGE_BYTES;
        #pragma unroll
        for (int j = 0; j < 8; j++) {
            const int idx = tid + 256 * j;
            const int mat = idx >> 9;
            const int rem = idx & 511;
            const int r = rem >> 2, c = rem & 3;
            cpasync16(sb + mat * MAT_BYTES + r * PITCH + c * 16,
                      bases[mat] + (size_t)r * DM + it * KSTAGE + c * 8);
        }
        CP_COMMIT();
    };

    float acc[2][8][4];
    #pragma unroll
    for (int i = 0; i < 2; i++)
        #pragma unroll
        for (int j = 0; j < 8; j++)
            #pragma unroll
            for (int q = 0; q < 4; q++) acc[i][j][q] = 0.f;

    ISSUE(0); ISSUE(1);

    for (int it = 0; it < NIT; ++it) {
        if (it == NIT - 1) { CP_WAIT0(); } else { CP_WAIT1(); }
        __syncthreads();

        const uint32_t sb = base + (it & 1) * STAGE_BYTES;
        #pragma unroll
        for (int kc = 0; kc < 2; kc++) {
            uint32_t Ah[2][4], Al[2][4];
            #pragma unroll
            for (int mf = 0; mf < 2; mf++) {
                const uint32_t aoff =
                    (uint32_t)((wm*32 + mf*16 + (lane & 15)) * PITCH
                               + kc*32 + (lane >> 4) * 16);
                ldm_x4(Ah[mf], sb + aoff);
                ldm_x4(Al[mf], sb + MAT_BYTES + aoff);
            }
            uint32_t Bh[4][4], Bl[4][4];
            #pragma unroll
            for (int g = 0; g < 4; g++) {
                const int quad = lane >> 3;
                const uint32_t boff =
                    (uint32_t)((wn*64 + g*16 + (quad >> 1) * 8 + (lane & 7)) * PITCH
                               + kc*32 + (quad & 1) * 16);
                ldm_x4(Bh[g], sb + 2*MAT_BYTES + boff);
                ldm_x4(Bl[g], sb + 3*MAT_BYTES + boff);
            }
            #pragma unroll
            for (int mf = 0; mf < 2; mf++)
                #pragma unroll
                for (int nb = 0; nb < 8; nb++)
                    mma16816(acc[mf][nb], Ah[mf], Bh[nb>>1][(nb&1)*2], Bh[nb>>1][(nb&1)*2+1]);
            #pragma unroll
            for (int mf = 0; mf < 2; mf++)
                #pragma unroll
                for (int nb = 0; nb < 8; nb++)
                    mma16816(acc[mf][nb], Al[mf], Bh[nb>>1][(nb&1)*2], Bh[nb>>1][(nb&1)*2+1]);
            #pragma unroll
            for (int mf = 0; mf < 2; mf++)
                #pragma unroll
                for (int nb = 0; nb < 8; nb++)
                    mma16816(acc[mf][nb], Ah[mf], Bl[nb>>1][(nb&1)*2], Bl[nb>>1][(nb&1)*2+1]);
        }
        __syncthreads();
        if (it + 2 < NIT) ISSUE(it + 2);
    }

    #pragma unroll
    for (int mf = 0; mf < 2; mf++)
        #pragma unroll
        for (int nb = 0; nb < 8; nb++)
            #pragma unroll
            for (int ci = 0; ci < 2; ci++) {
                const int m = by*128 + wm*32 + mf*16 + (lane >> 2) + ci*8;
                const int n = bx*128 + wn*64 + nb*8 + (lane & 3) * 2;
                float2 v;
                v.x = acc[mf][nb][2*ci+0] + bias[n];
                v.y = acc[mf][nb][2*ci+1] + bias[n+1];
                *(float2*)&Cout[(size_t)m * DM + n] = v;
            }
}

// ---------------------------------------------------------------------------
// RoPE: read g_q/g_k fp32, write rotated bf16 hi/lo
// ---------------------------------------------------------------------------
__global__ void __launch_bounds__(256) rope_kernel(
    const float* __restrict__ cosp, const float* __restrict__ sinp)
{
    const int idx  = blockIdx.x * 256 + threadIdx.x;   // < NB*NH*SQ*40
    const int d    = idx % 40;
    const int rest = idx / 40;
    const int ss   = rest & (SQ - 1);
    const int bh   = rest >> 10;
    const size_t base = ((size_t)bh * SQ + ss) * HD;
    const float c1 = cosp[ss*HD + d],      s1 = sinp[ss*HD + d];
    const float c2 = cosp[ss*HD + d + 40], s2 = sinp[ss*HD + d + 40];

    float q1 = g_q[base + d], q2 = g_q[base + d + 40];
    float o1 = q1*c1 - q2*s1;
    float o2 = q2*c2 + q1*s2;
    __nv_bfloat16 h;
    h = __float2bfloat16_rn(o1); qh_g[base+d]    = h; ql_g[base+d]    = __float2bfloat16_rn(o1 - __bfloat162float(h));
    h = __float2bfloat16_rn(o2); qh_g[base+d+40] = h; ql_g[base+d+40] = __float2bfloat16_rn(o2 - __bfloat162float(h));

    float k1 = g_k[base + d], k2 = g_k[base + d + 40];
    o1 = k1*c1 - k2*s1;
    o2 = k2*c2 + k1*s2;
    h = __float2bfloat16_rn(o1); kh_g[base+d]    = h; kl_g[base+d]    = __float2bfloat16_rn(o1 - __bfloat162float(h));
    h = __float2bfloat16_rn(o2); kh_g[base+d+40] = h; kl_g[base+d+40] = __float2bfloat16_rn(o2 - __bfloat162float(h));
}

// ===========================================================================
// Flash attention on mma.sync (exact round-6 version).
// ===========================================================================
#define APITCH 176                        // bytes per 80-elem bf16 row (+pad)
#define AMATQ (128*APITCH)                // 22528 per Q matrix (128 rows)
#define AMAT64 (64*APITCH)                // 11264 per KV matrix (64 rows)
#define AQH 0
#define AQL AMATQ
#define AKV0 (2*AMATQ)                    // 45056
#define KV_STAGE (4*AMAT64)               // 45056
#define ATTN_SMEM (2*AMATQ + 2*KV_STAGE)  // 135168

__global__ void __launch_bounds__(256) attn_tc()
{
    extern __shared__ char dsm_raw[];
    const uint32_t base = s2u(dsm_raw);

    const int tid = threadIdx.x;
    const int w = tid >> 5, lane = tid & 31;
    const int qt = blockIdx.x, bh = blockIdx.y;
    const int b = bh >> 4, h = bh & 15;
    const float scale = 0.11180339887498948f;  // 1/sqrt(80)

    const size_t krow0base = (size_t)bh * SQ;

    auto ISSUE_KV = [&](int kt) {
        const uint32_t sb = base + AKV0 + (kt & 1) * KV_STAGE;
        const size_t krow0 = krow0base + kt * 64;
        const __nv_bfloat16* srcs[4] = { kh_g, kl_g, vh_g, vl_g };
        #pragma unroll
        for (int j = 0; j < 10; j++) {
            const int idx = tid + 256 * j;   // 0..2559
            const int mat = idx / 640;
            const int rem = idx - mat * 640;
            const int r = rem / 10, c = rem - r * 10;
            cpasync16(sb + mat * AMAT64 + r * APITCH + c * 16,
                      srcs[mat] + (krow0 + r) * HD + c * 8);
        }
        CP_COMMIT();
    };

    {
        const size_t qrow0 = krow0base + qt * 128;
        #pragma unroll
        for (int j = 0; j < 10; j++) {
            const int idx = tid + 256 * j;
            const int mat = idx / 1280;
            const int rem = idx - mat * 1280;
            const int r = rem / 10, c = rem - r * 10;
            cpasync16(base + (mat ? AQL : AQH) + r * APITCH + c * 16,
                      (mat ? ql_g : qh_g) + (qrow0 + r) * HD + c * 8);
        }
        CP_COMMIT();
    }
    ISSUE_KV(0);

    float oacc[10][4];
    #pragma unroll
    for (int i = 0; i < 10; i++)
        #pragma unroll
        for (int j = 0; j < 4; j++) oacc[i][j] = 0.f;
    float m0 = -1e30f, m1 = -1e30f, l0 = 0.f, l1 = 0.f;

    for (int kt = 0; kt < 16; kt++) {
        if (kt + 1 < 16) { ISSUE_KV(kt + 1); CP_WAIT1(); } else { CP_WAIT0(); }
        __syncthreads();

        const uint32_t kvb = base + AKV0 + (kt & 1) * KV_STAGE;
        const uint32_t sKH = kvb, sKL = kvb + AMAT64;
        const uint32_t sVH = kvb + 2*AMAT64, sVL = kvb + 3*AMAT64;

        float sacc[8][4];
        #pragma unroll
        for (int i = 0; i < 8; i++)
            #pragma unroll
            for (int j = 0; j < 4; j++) sacc[i][j] = 0.f;

        #pragma unroll
        for (int kc = 0; kc < 5; kc++) {
            uint32_t Aah[4], Aal[4];
            const uint32_t aoff =
                (uint32_t)((w*16 + (lane & 15)) * APITCH + kc*32 + (lane >> 4) * 16);
            ldm_x4(Aah, base + AQH + aoff);
            ldm_x4(Aal, base + AQL + aoff);
            uint32_t Bh4[4][4], Bl4[4][4];
            #pragma unroll
            for (int g = 0; g < 4; g++) {
                const int quad = lane >> 3;
                const uint32_t boff =
                    (uint32_t)((g*16 + (quad >> 1) * 8 + (lane & 7)) * APITCH
                               + kc*32 + (quad & 1) * 16);
                ldm_x4(Bh4[g], sKH + boff);
                ldm_x4(Bl4[g], sKL + boff);
            }
            #pragma unroll
            for (int g = 0; g < 4; g++)
                #pragma unroll
                for (int hh = 0; hh < 2; hh++)
                    mma16816(sacc[g*2+hh], Aah, Bh4[g][2*hh], Bh4[g][2*hh+1]);
            #pragma unroll
            for (int g = 0; g < 4; g++)
                #pragma unroll
                for (int hh = 0; hh < 2; hh++)
                    mma16816(sacc[g*2+hh], Aal, Bh4[g][2*hh], Bh4[g][2*hh+1]);
            #pragma unroll
            for (int g = 0; g < 4; g++)
                #pragma unroll
                for (int hh = 0; hh < 2; hh++)
                    mma16816(sacc[g*2+hh], Aah, Bl4[g][2*hh], Bl4[g][2*hh+1]);
        }

        #pragma unroll
        for (int nb = 0; nb < 8; nb++)
            #pragma unroll
            for (int j = 0; j < 4; j++) sacc[nb][j] *= scale;

        float mx0 = -1e30f, mx1 = -1e30f;
        #pragma unroll
        for (int nb = 0; nb < 8; nb++) {
            mx0 = fmaxf(mx0, fmaxf(sacc[nb][0], sacc[nb][1]));
            mx1 = fmaxf(mx1, fmaxf(sacc[nb][2], sacc[nb][3]));
        }
        mx0 = fmaxf(mx0, __shfl_xor_sync(0xffffffffu, mx0, 1));
        mx0 = fmaxf(mx0, __shfl_xor_sync(0xffffffffu, mx0, 2));
        mx1 = fmaxf(mx1, __shfl_xor_sync(0xffffffffu, mx1, 1));
        mx1 = fmaxf(mx1, __shfl_xor_sync(0xffffffffu, mx1, 2));

        const float mn0 = fmaxf(m0, mx0), mn1 = fmaxf(m1, mx1);
        const float al0 = __expf(m0 - mn0), al1 = __expf(m1 - mn1);
        m0 = mn0; m1 = mn1;

        float rs0 = 0.f, rs1 = 0.f;
        #pragma unroll
        for (int nb = 0; nb < 8; nb++) {
            sacc[nb][0] = __expf(sacc[nb][0] - m0);
            sacc[nb][1] = __expf(sacc[nb][1] - m0);
            sacc[nb][2] = __expf(sacc[nb][2] - m1);
            sacc[nb][3] = __expf(sacc[nb][3] - m1);
            rs0 += sacc[nb][0] + sacc[nb][1];
            rs1 += sacc[nb][2] + sacc[nb][3];
        }
        rs0 += __shfl_xor_sync(0xffffffffu, rs0, 1);
        rs0 += __shfl_xor_sync(0xffffffffu, rs0, 2);
        rs1 += __shfl_xor_sync(0xffffffffu, rs1, 1);
        rs1 += __shfl_xor_sync(0xffffffffu, rs1, 2);
        l0 = l0 * al0 + rs0;
        l1 = l1 * al1 + rs1;

        #pragma unroll
        for (int nb = 0; nb < 10; nb++) {
            oacc[nb][0] *= al0; oacc[nb][1] *= al0;
            oacc[nb][2] *= al1; oacc[nb][3] *= al1;
        }

        #pragma unroll
        for (int kc = 0; kc < 4; kc++) {
            uint32_t Pa_h[4], Pa_l[4];
            #pragma unroll
            for (int half2i = 0; half2i < 2; half2i++) {
                const int nb = 2*kc + half2i;
                float f0 = sacc[nb][0], f1 = sacc[nb][1];
                float f2 = sacc[nb][2], f3 = sacc[nb][3];
                float h0 = __bfloat162float(__float2bfloat16_rn(f0));
                float h1 = __bfloat162float(__float2bfloat16_rn(f1));
                float h2 = __bfloat162float(__float2bfloat16_rn(f2));
                float h3 = __bfloat162float(__float2bfloat16_rn(f3));
                Pa_h[2*half2i+0] = packbf(h0, h1);
                Pa_h[2*half2i+1] = packbf(h2, h3);
                Pa_l[2*half2i+0] = packbf(f0 - h0, f1 - h1);
                Pa_l[2*half2i+1] = packbf(f2 - h2, f3 - h3);
            }
            uint32_t Vh4[5][4], Vl4[5][4];
            #pragma unroll
            for (int vg = 0; vg < 5; vg++) {
                const int vrow = kc*16 + ((lane >> 3) & 1) * 8 + (lane & 7);
                const int vcol = vg*16 + (lane >> 4) * 8;
                const uint32_t voff = (uint32_t)(vrow * APITCH + vcol * 2);
                ldm_x4_t(Vh4[vg], sVH + voff);
                ldm_x4_t(Vl4[vg], sVL + voff);
            }
            #pragma unroll
            for (int vg = 0; vg < 5; vg++)
                #pragma unroll
                for (int hh = 0; hh < 2; hh++)
                    mma16816(oacc[vg*2+hh], Pa_h, Vh4[vg][2*hh], Vh4[vg][2*hh+1]);
            #pragma unroll
            for (int vg = 0; vg < 5; vg++)
                #pragma unroll
                for (int hh = 0; hh < 2; hh++)
                    mma16816(oacc[vg*2+hh], Pa_l, Vh4[vg][2*hh], Vh4[vg][2*hh+1]);
            #pragma unroll
            for (int vg = 0; vg < 5; vg++)
                #pragma unroll
                for (int hh = 0; hh < 2; hh++)
                    mma16816(oacc[vg*2+hh], Pa_h, Vl4[vg][2*hh], Vl4[vg][2*hh+1]);
        }
        __syncthreads();
    }

    const float inv0 = 1.f / l0, inv1 = 1.f / l1;
    const int s0 = qt*128 + w*16 + (lane >> 2);
    const int s1 = s0 + 8;
    #pragma unroll
    for (int nb = 0; nb < 10; nb++) {
        const int d = nb*8 + (lane & 3) * 2;
        {
            const size_t di = ((size_t)b * SQ + s0) * DM + h * HD + d;
            float o0 = oacc[nb][0] * inv0, o1 = oacc[nb][1] * inv0;
            __nv_bfloat16 h0 = __float2bfloat16_rn(o0);
            __nv_bfloat16 h1 = __float2bfloat16_rn(o1);
            *(__nv_bfloat162*)&ch_g[di] = __nv_bfloat162(h0, h1);
            *(__nv_bfloat162*)&cl_g[di] = __floats2bfloat162_rn(
                o0 - __bfloat162float(h0), o1 - __bfloat162float(h1));
        }
        {
            const size_t di = ((size_t)b * SQ + s1) * DM + h * HD + d;
            float o0 = oacc[nb][2] * inv1, o1 = oacc[nb][3] * inv1;
            __nv_bfloat16 h0 = __float2bfloat16_rn(o0);
            __nv_bfloat16 h1 = __float2bfloat16_rn(o1);
            *(__nv_bfloat162*)&ch_g[di] = __nv_bfloat162(h0, h1);
            *(__nv_bfloat162*)&cl_g[di] = __floats2bfloat162_rn(
                o0 - __bfloat162float(h0), o1 - __bfloat162float(h1));
        }
    }
}

// ---------------------------------------------------------------------------
extern "C" void kernel_launch(void* const* d_in, const int* in_sizes, int n_in,
                              void* d_out, int out_size)
{
    (void)in_sizes; (void)n_in; (void)out_size;
    const float* x     = (const float*)d_in[0];
    const float* cosp  = (const float*)d_in[1];
    const float* sinp  = (const float*)d_in[2];
    const float* Wqkv  = (const float*)d_in[3];
    const float* bqkv  = (const float*)d_in[4];
    const float* Wproj = (const float*)d_in[5];
    const float* bproj = (const float*)d_in[6];
    float* out = (float*)d_out;

    cudaFuncSetAttribute(gemm_qkv_i8,
                         cudaFuncAttributeMaxDynamicSharedMemorySize, IGEMM_DSMEM);
    cudaFuncSetAttribute(gemm_proj,
                         cudaFuncAttributeMaxDynamicSharedMemorySize, GEMM_DSMEM);
    cudaFuncSetAttribute(attn_tc,
                         cudaFuncAttributeMaxDynamicSharedMemorySize, ATTN_SMEM);

    int8_t *xq1, *xq2, *wq1, *wq2;
    float *sax, *sbw;
    __nv_bfloat16 *wph, *wpl;
    cudaGetSymbolAddress((void**)&xq1, xq1_g);
    cudaGetSymbolAddress((void**)&xq2, xq2_g);
    cudaGetSymbolAddress((void**)&wq1, wq1_g);
    cudaGetSymbolAddress((void**)&wq2, wq2_g);
    cudaGetSymbolAddress((void**)&sax, sax_g);
    cudaGetSymbolAddress((void**)&sbw, sbw_g);
    cudaGetSymbolAddress((void**)&wph, wph_g);
    cudaGetSymbolAddress((void**)&wpl, wpl_g);

    // 0) quantize x, Wqkv (int8 2-digit); split Wproj (bf16 hi/lo)
    quant_kernel<<<MTOT, 128>>>(x, xq1, xq2, sax);
    quant_kernel<<<NQKV, 128>>>(Wqkv, wq1, wq2, sbw);
    split_kernel<<<(DM*DM/4 + 255)/256, 256>>>(Wproj, wph, wpl, DM*DM/4);
    // 1) QKV GEMM (int8): q,k fp32 head-major + v bf16 hi/lo
    gemm_qkv_i8<<<dim3(NQKV/64, MTOT/128), 256, IGEMM_DSMEM>>>(bqkv);
    // 2) RoPE -> qh/ql, kh/kl
    rope_kernel<<<(NB*NH*SQ*40)/256, 256>>>(cosp, sinp);
    // 3) attention -> ch/cl
    attn_tc<<<dim3(SQ/128, NB*NH), 256, ATTN_SMEM>>>();
    // 4) output projection (bf16 3-pass)
    gemm_proj<<<dim3(DM/128, MTOT/128), 256, GEMM_DSMEM>>>(bproj, out);
}

// round 10
// speedup vs baseline: 1.7103x; 1.1683x over previous
#include <cuda_runtime.h>
#include <cuda_bf16.h>
#include <cstdint>

#define NB 4
#define SQ 1024
#define DM 1280
#define NH 16
#define HD 80
#define MTOT (NB*SQ)      // 4096
#define NQKV (3*DM)       // 3840
#define NROWS (NB*NH*SQ)  // 65536
#define QPAD 96           // int8 head rows padded 80 -> 96

// ---------------------------------------------------------------------------
// Scratch (__device__ globals; allocation-free rule)
// ---------------------------------------------------------------------------
__device__ float g_q[NROWS*HD];
__device__ float g_k[NROWS*HD];
__device__ float g_ctx[MTOT*DM];

// int8 2-digit operands (xq*/sax reused for ctx; wq*/sbw reused for Wproj)
__device__ int8_t xq1_g[MTOT*DM],  xq2_g[MTOT*DM];
__device__ int8_t wq1_g[NQKV*DM],  wq2_g[NQKV*DM];
__device__ float  sax_g[MTOT];
__device__ float  sbw_g[NQKV];

// int8 2-digit rotated q/k + per-row scales
__device__ int8_t qq1_g[NROWS*QPAD], qq2_g[NROWS*QPAD];
__device__ int8_t kq1_g[NROWS*QPAD], kq2_g[NROWS*QPAD];
__device__ float  sq_g[NROWS], sk_g[NROWS];

// bf16 hi/lo V (PV stays bf16)
__device__ __nv_bfloat16 vh_g[NROWS*HD], vl_g[NROWS*HD];

// ---------------------------------------------------------------------------
// helpers
// ---------------------------------------------------------------------------
__device__ __forceinline__ uint32_t s2u(const void* p) {
    uint32_t a;
    asm("{ .reg .u64 t; cvta.to.shared.u64 t, %1; cvt.u32.u64 %0, t; }"
        : "=r"(a) : "l"(p));
    return a;
}
__device__ __forceinline__ void ldm_x4(uint32_t* r, uint32_t addr) {
    asm volatile("ldmatrix.sync.aligned.m8n8.x4.shared.b16 {%0,%1,%2,%3}, [%4];"
        : "=r"(r[0]), "=r"(r[1]), "=r"(r[2]), "=r"(r[3]) : "r"(addr));
}
__device__ __forceinline__ void ldm_x4_t(uint32_t* r, uint32_t addr) {
    asm volatile("ldmatrix.sync.aligned.m8n8.x4.trans.shared.b16 {%0,%1,%2,%3}, [%4];"
        : "=r"(r[0]), "=r"(r[1]), "=r"(r[2]), "=r"(r[3]) : "r"(addr));
}
__device__ __forceinline__ void mma16816(float* c, const uint32_t* a,
                                         uint32_t b0, uint32_t b1) {
    asm volatile(
        "mma.sync.aligned.m16n8k16.row.col.f32.bf16.bf16.f32 "
        "{%0,%1,%2,%3}, {%4,%5,%6,%7}, {%8,%9}, {%0,%1,%2,%3};"
        : "+f"(c[0]), "+f"(c[1]), "+f"(c[2]), "+f"(c[3])
        : "r"(a[0]), "r"(a[1]), "r"(a[2]), "r"(a[3]), "r"(b0), "r"(b1));
}
__device__ __forceinline__ void mma_s8(int* c, const uint32_t* a,
                                       uint32_t b0, uint32_t b1) {
    asm volatile(
        "mma.sync.aligned.m16n8k32.row.col.s32.s8.s8.s32 "
        "{%0,%1,%2,%3}, {%4,%5,%6,%7}, {%8,%9}, {%0,%1,%2,%3};"
        : "+r"(c[0]), "+r"(c[1]), "+r"(c[2]), "+r"(c[3])
        : "r"(a[0]), "r"(a[1]), "r"(a[2]), "r"(a[3]), "r"(b0), "r"(b1));
}
__device__ __forceinline__ uint32_t packbf(float a, float b) {
    __nv_bfloat162 t = __floats2bfloat162_rn(a, b);
    return *reinterpret_cast<uint32_t*>(&t);
}
__device__ __forceinline__ void cpasync16(uint32_t dst, const void* src) {
    asm volatile("cp.async.ca.shared.global [%0], [%1], 16;"
        :: "r"(dst), "l"(src) : "memory");
}
#define CP_COMMIT() asm volatile("cp.async.commit_group;" ::: "memory")
#define CP_WAIT0()  asm volatile("cp.async.wait_group 0;" ::: "memory")
#define CP_WAIT1()  asm volatile("cp.async.wait_group 1;" ::: "memory")

// ---------------------------------------------------------------------------
// fp32 -> int8 2-digit row quantization: v = s*(d1 + d2/250), s = rowmax/120.
// One block of 128 threads per row of DM cols.
// ---------------------------------------------------------------------------
__global__ void __launch_bounds__(128) quant_kernel(
    const float* __restrict__ src, int8_t* __restrict__ d1,
    int8_t* __restrict__ d2, float* __restrict__ scale)
{
    const int row = blockIdx.x;
    const int tid = threadIdx.x;
    const float* p = src + (size_t)row * DM;
    float mx = 0.f;
    for (int i = tid; i < DM; i += 128) mx = fmaxf(mx, fabsf(p[i]));
    #pragma unroll
    for (int off = 16; off >= 1; off >>= 1)
        mx = fmaxf(mx, __shfl_xor_sync(0xffffffffu, mx, off));
    __shared__ float smx[4];
    if ((tid & 31) == 0) smx[tid >> 5] = mx;
    __syncthreads();
    mx = fmaxf(fmaxf(smx[0], smx[1]), fmaxf(smx[2], smx[3]));
    const float s = (mx > 0.f) ? mx * (1.f / 120.f) : 1.f;
    const float inv = 1.f / s;
    for (int i = tid; i < DM; i += 128) {
        const float f  = p[i] * inv;
        const float q1 = rintf(f);
        const float q2 = rintf(250.f * (f - q1));
        d1[(size_t)row * DM + i] = (int8_t)(int)q1;
        d2[(size_t)row * DM + i] = (int8_t)(int)q2;
    }
    if (tid == 0) scale[row] = s;
}

// ===========================================================================
// int8 2-digit GEMM core: C = sa[m]*sb[n]*(P + X/250) + bias[n].
// CTA 128(M)x64(N), 256 thr, 8 warps of 32x32, K-stage 128 int8, 2-stage.
// PROJ=false: QKV (scatter q,k fp32 + v bf16 hi/lo). PROJ=true: dense out.
// ===========================================================================
#define IK 128
#define IPITCH 144
#define IOFF_A2 (128*IPITCH)
#define IOFF_B1 (2*128*IPITCH)
#define IOFF_B2 (IOFF_B1 + 64*IPITCH)
#define ISTAGE (IOFF_B2 + 64*IPITCH)
#define IGEMM_DSMEM (2*ISTAGE)         // 110592

template<bool PROJ>
__global__ void __launch_bounds__(256, 2) gemm_i8(
    const int8_t* __restrict__ A1, const int8_t* __restrict__ A2,
    const int8_t* __restrict__ B1, const int8_t* __restrict__ B2,
    const float* __restrict__ sa_v, const float* __restrict__ sb_v,
    const float* __restrict__ bias, float* __restrict__ Cout)
{
    extern __shared__ char dsm_raw[];
    const uint32_t base = s2u(dsm_raw);

    const int tid  = threadIdx.x;
    const int wid  = tid >> 5, lane = tid & 31;
    const int bx = blockIdx.x, by = blockIdx.y;
    const int wm = wid >> 1, wn = wid & 1;    // warp tile 32(M) x 32(N)

    const int8_t* a1p = A1 + (size_t)(by * 128) * DM;
    const int8_t* a2p = A2 + (size_t)(by * 128) * DM;
    const int8_t* b1p = B1 + (size_t)(bx * 64) * DM;
    const int8_t* b2p = B2 + (size_t)(bx * 64) * DM;

    auto ISSUE = [&](int it) {
        const uint32_t sb = base + (it & 1) * ISTAGE;
        const int kof = it * IK;
        #pragma unroll
        for (int j = 0; j < 12; j++) {
            const int idx = tid + 256 * j;
            int local; uint32_t moff; const int8_t* srcp;
            if (j < 4)       { local = idx;        moff = 0;       srcp = a1p; }
            else if (j < 8)  { local = idx - 1024; moff = IOFF_A2; srcp = a2p; }
            else if (j < 10) { local = idx - 2048; moff = IOFF_B1; srcp = b1p; }
            else             { local = idx - 2560; moff = IOFF_B2; srcp = b2p; }
            const int r = local >> 3, c = local & 7;
            cpasync16(sb + moff + r * IPITCH + c * 16,
                      srcp + (size_t)r * DM + kof + c * 16);
        }
        CP_COMMIT();
    };

    int accP[2][4][4], accX[2][4][4];
    #pragma unroll
    for (int i = 0; i < 2; i++)
        #pragma unroll
        for (int j = 0; j < 4; j++)
            #pragma unroll
            for (int q = 0; q < 4; q++) { accP[i][j][q] = 0; accX[i][j][q] = 0; }

    ISSUE(0); ISSUE(1);

    const int NITI = DM / IK;
    for (int it = 0; it < NITI; ++it) {
        if (it == NITI - 1) { CP_WAIT0(); } else { CP_WAIT1(); }
        __syncthreads();

        const uint32_t sb = base + (it & 1) * ISTAGE;
        #pragma unroll
        for (int kc = 0; kc < 4; kc++) {
            uint32_t Ad1[2][4], Ad2[2][4];
            #pragma unroll
            for (int mf = 0; mf < 2; mf++) {
                const uint32_t aoff =
                    (uint32_t)((wm*32 + mf*16 + (lane & 15)) * IPITCH
                               + kc*32 + (lane >> 4) * 16);
                ldm_x4(Ad1[mf], sb + aoff);
                ldm_x4(Ad2[mf], sb + IOFF_A2 + aoff);
            }
            uint32_t Bd1[2][4], Bd2[2][4];
            #pragma unroll
            for (int g = 0; g < 2; g++) {
                const int quad = lane >> 3;
                const uint32_t boff =
                    (uint32_t)((wn*32 + g*16 + (quad >> 1) * 8 + (lane & 7)) * IPITCH
                               + kc*32 + (quad & 1) * 16);
                ldm_x4(Bd1[g], sb + IOFF_B1 + boff);
                ldm_x4(Bd2[g], sb + IOFF_B2 + boff);
            }
            #pragma unroll
            for (int mf = 0; mf < 2; mf++)
                #pragma unroll
                for (int nb = 0; nb < 4; nb++)
                    mma_s8(accP[mf][nb], Ad1[mf], Bd1[nb>>1][(nb&1)*2], Bd1[nb>>1][(nb&1)*2+1]);
            #pragma unroll
            for (int mf = 0; mf < 2; mf++)
                #pragma unroll
                for (int nb = 0; nb < 4; nb++)
                    mma_s8(accX[mf][nb], Ad1[mf], Bd2[nb>>1][(nb&1)*2], Bd2[nb>>1][(nb&1)*2+1]);
            #pragma unroll
            for (int mf = 0; mf < 2; mf++)
                #pragma unroll
                for (int nb = 0; nb < 4; nb++)
                    mma_s8(accX[mf][nb], Ad2[mf], Bd1[nb>>1][(nb&1)*2], Bd1[nb>>1][(nb&1)*2+1]);
        }
        __syncthreads();
        if (it + 2 < NITI) ISSUE(it + 2);
    }

    #pragma unroll
    for (int mf = 0; mf < 2; mf++)
        #pragma unroll
        for (int nb = 0; nb < 4; nb++)
            #pragma unroll
            for (int ci = 0; ci < 2; ci++) {
                const int m = by*128 + wm*32 + mf*16 + (lane >> 2) + ci*8;
                const int n = bx*64 + wn*32 + nb*8 + (lane & 3) * 2;
                const float sa = sa_v[m];
                float2 v;
                v.x = sa * sb_v[n]   * ((float)accP[mf][nb][2*ci+0]
                        + (float)accX[mf][nb][2*ci+0] * 0.004f) + bias[n];
                v.y = sa * sb_v[n+1] * ((float)accP[mf][nb][2*ci+1]
                        + (float)accX[mf][nb][2*ci+1] * 0.004f) + bias[n+1];
                if (PROJ) {
                    *(float2*)&Cout[(size_t)m * DM + n] = v;
                } else {
                    const int sel = n / DM;
                    const int r2  = n - sel * DM;
                    const int h   = r2 / HD;
                    const int dd  = r2 - h * HD;
                    const int bb  = m >> 10;
                    const int ss  = m & (SQ - 1);
                    const size_t di = (((size_t)bb * NH + h) * SQ + ss) * HD + dd;
                    if (sel == 0)      *(float2*)&g_q[di] = v;
                    else if (sel == 1) *(float2*)&g_k[di] = v;
                    else {
                        __nv_bfloat16 h0 = __float2bfloat16_rn(v.x);
                        __nv_bfloat16 h1 = __float2bfloat16_rn(v.y);
                        *(__nv_bfloat162*)&vh_g[di] = __nv_bfloat162(h0, h1);
                        *(__nv_bfloat162*)&vl_g[di] = __floats2bfloat162_rn(
                            v.x - __bfloat162float(h0), v.y - __bfloat162float(h1));
                    }
                }
            }
}

// ---------------------------------------------------------------------------
// RoPE + int8 2-digit quantization. One warp per (b,h,s) row of 80.
// Writes qq1/qq2/kq1/kq2 (rows padded to 96 with zeros) + sq/sk scales.
// ---------------------------------------------------------------------------
__global__ void __launch_bounds__(256) rope_quant(
    const float* __restrict__ cosp, const float* __restrict__ sinp)
{
    const int row  = (blockIdx.x << 3) + (threadIdx.x >> 5);   // < NROWS
    const int lane = threadIdx.x & 31;
    const int ss   = row & (SQ - 1);
    const size_t base = (size_t)row * HD;

    const int d0 = lane;                 // 0..31 (< 40)
    const bool two = lane < 8;           // second pair d = lane+32 (< 40)

    const float c1 = cosp[ss*HD + d0],      s1 = sinp[ss*HD + d0];
    const float c2 = cosp[ss*HD + d0 + 40], s2 = sinp[ss*HD + d0 + 40];
    float a, b2;

    a = g_q[base + d0]; b2 = g_q[base + d0 + 40];
    float qo1 = a*c1 - b2*s1, qo2 = b2*c2 + a*s2;
    a = g_k[base + d0]; b2 = g_k[base + d0 + 40];
    float ko1 = a*c1 - b2*s1, ko2 = b2*c2 + a*s2;

    float qo3 = 0.f, qo4 = 0.f, ko3 = 0.f, ko4 = 0.f;
    if (two) {
        const int d = lane + 32;
        const float cc1 = cosp[ss*HD + d],      ss1 = sinp[ss*HD + d];
        const float cc2 = cosp[ss*HD + d + 40], ss2 = sinp[ss*HD + d + 40];
        a = g_q[base + d]; b2 = g_q[base + d + 40];
        qo3 = a*cc1 - b2*ss1; qo4 = b2*cc2 + a*ss2;
        a = g_k[base + d]; b2 = g_k[base + d + 40];
        ko3 = a*cc1 - b2*ss1; ko4 = b2*cc2 + a*ss2;
    }

    float qm = fmaxf(fmaxf(fabsf(qo1), fabsf(qo2)), fmaxf(fabsf(qo3), fabsf(qo4)));
    float km = fmaxf(fmaxf(fabsf(ko1), fabsf(ko2)), fmaxf(fabsf(ko3), fabsf(ko4)));
    #pragma unroll
    for (int off = 16; off >= 1; off >>= 1) {
        qm = fmaxf(qm, __shfl_xor_sync(0xffffffffu, qm, off));
        km = fmaxf(km, __shfl_xor_sync(0xffffffffu, km, off));
    }
    const float sq = (qm > 0.f) ? qm * (1.f/120.f) : 1.f;
    const float sk = (km > 0.f) ? km * (1.f/120.f) : 1.f;
    const float iq = 1.f / sq, ik = 1.f / sk;

    const size_t rb = (size_t)row * QPAD;
    auto putq = [&](int d, float v) {
        const float f = v * iq;
        const float q1 = rintf(f);
        qq1_g[rb + d] = (int8_t)(int)q1;
        qq2_g[rb + d] = (int8_t)(int)rintf(250.f * (f - q1));
    };
    auto putk = [&](int d, float v) {
        const float f = v * ik;
        const float q1 = rintf(f);
        kq1_g[rb + d] = (int8_t)(int)q1;
        kq2_g[rb + d] = (int8_t)(int)rintf(250.f * (f - q1));
    };
    putq(d0, qo1); putq(d0 + 40, qo2);
    putk(d0, ko1); putk(d0 + 40, ko2);
    if (two) {
        putq(d0 + 32, qo3); putq(d0 + 72, qo4);
        putk(d0 + 32, ko3); putk(d0 + 72, ko4);
    }
    if (lane < 16) {  // zero pad cols 80..95
        qq1_g[rb + 80 + lane] = 0; qq2_g[rb + 80 + lane] = 0;
        kq1_g[rb + 80 + lane] = 0; kq2_g[rb + 80 + lane] = 0;
    }
    if (lane == 0) { sq_g[row] = sq; sk_g[row] = sk; }
}

// ===========================================================================
// Flash attention: S-phase int8 2-digit (k32), PV bf16 3-pass.
// CTA = (q-tile 128 rows, bh), 8 warps. Double-buffered K/V. fp32 ctx out.
// ===========================================================================
#define QIP 112                          // int8 row pitch in smem (96 + 16)
#define AQ1 0                            // QI1: 128*112 = 14336
#define AQ2 14336
#define AKVQ 28672
#define SK1o 0
#define SK2o 7168
#define SVHo 14336
#define SVLo 25600
#define SSKo 36864                       // 64 floats
#define KVSTG 37120
#define ATTN_SMEM (AKVQ + 2*KVSTG)       // 102912
#define APITCH 176                       // bf16 V row pitch

__global__ void __launch_bounds__(256) attn_tc()
{
    extern __shared__ char dsm_raw[];
    const uint32_t base = s2u(dsm_raw);

    const int tid = threadIdx.x;
    const int w = tid >> 5, lane = tid & 31;
    const int qt = blockIdx.x, bh = blockIdx.y;
    const int b = bh >> 4, h = bh & 15;
    const float scale = 0.11180339887498948f;  // 1/sqrt(80)

    const size_t row0 = (size_t)bh * SQ;
    const size_t qrow0 = row0 + qt * 128;

    auto ISSUE_KV = [&](int kt) {
        const uint32_t sb = base + AKVQ + (kt & 1) * KVSTG;
        const size_t kr = row0 + kt * 64;
        #pragma unroll
        for (int j = 0; j < 9; j++) {
            const int idx = tid + 256 * j;        // 0..2063 used
            if (idx < 384) {
                const int r = idx / 6, c = idx - r * 6;
                cpasync16(sb + SK1o + r * QIP + c * 16,
                          kq1_g + (kr + r) * QPAD + c * 16);
            } else if (idx < 768) {
                const int l = idx - 384, r = l / 6, c = l - r * 6;
                cpasync16(sb + SK2o + r * QIP + c * 16,
                          kq2_g + (kr + r) * QPAD + c * 16);
            } else if (idx < 1408) {
                const int l = idx - 768, r = l / 10, c = l - r * 10;
                cpasync16(sb + SVHo + r * APITCH + c * 16,
                          vh_g + (kr + r) * HD + c * 8);
            } else if (idx < 2048) {
                const int l = idx - 1408, r = l / 10, c = l - r * 10;
                cpasync16(sb + SVLo + r * APITCH + c * 16,
                          vl_g + (kr + r) * HD + c * 8);
            } else if (idx < 2064) {
                const int l = idx - 2048;
                cpasync16(sb + SSKo + l * 16, sk_g + kr + l * 4);
            }
        }
        CP_COMMIT();
    };

    // Q int8 tiles (once): 128 rows x 6 chunks x 2 mats = 1536
    {
        #pragma unroll
        for (int j = 0; j < 6; j++) {
            const int idx = tid + 256 * j;
            const int mat = idx / 768;
            const int rem = idx - mat * 768;
            const int r = rem / 6, c = rem - r * 6;
            cpasync16(base + (mat ? AQ2 : AQ1) + r * QIP + c * 16,
                      (mat ? qq2_g : qq1_g) + (qrow0 + r) * QPAD + c * 16);
        }
        CP_COMMIT();
    }
    ISSUE_KV(0);

    const float sq0 = sq_g[qrow0 + w*16 + (lane >> 2)];
    const float sq1 = sq_g[qrow0 + w*16 + (lane >> 2) + 8];

    float oacc[10][4];
    #pragma unroll
    for (int i = 0; i < 10; i++)
        #pragma unroll
        for (int j = 0; j < 4; j++) oacc[i][j] = 0.f;
    float m0 = -1e30f, m1 = -1e30f, l0 = 0.f, l1 = 0.f;

    for (int kt = 0; kt < 16; kt++) {
        if (kt + 1 < 16) { ISSUE_KV(kt + 1); CP_WAIT1(); } else { CP_WAIT0(); }
        __syncthreads();

        const uint32_t kvb = base + AKVQ + (kt & 1) * KVSTG;
        const float* skf = (const float*)(dsm_raw + AKVQ + (kt & 1) * KVSTG + SSKo);

        // ---- S = Q K^T, int8 2-digit (3 k-chunks x 3 passes) ----
        int accP[8][4], accX[8][4];
        #pragma unroll
        for (int i = 0; i < 8; i++)
            #pragma unroll
            for (int j = 0; j < 4; j++) { accP[i][j] = 0; accX[i][j] = 0; }

        #pragma unroll
        for (int kc = 0; kc < 3; kc++) {
            uint32_t Ad1[4], Ad2[4];
            const uint32_t aoff =
                (uint32_t)((w*16 + (lane & 15)) * QIP + kc*32 + (lane >> 4) * 16);
            ldm_x4(Ad1, base + AQ1 + aoff);
            ldm_x4(Ad2, base + AQ2 + aoff);
            uint32_t Bd1[4][4], Bd2[4][4];
            #pragma unroll
            for (int g = 0; g < 4; g++) {
                const int quad = lane >> 3;
                const uint32_t boff =
                    (uint32_t)((g*16 + (quad >> 1) * 8 + (lane & 7)) * QIP
                               + kc*32 + (quad & 1) * 16);
                ldm_x4(Bd1[g], kvb + SK1o + boff);
                ldm_x4(Bd2[g], kvb + SK2o + boff);
            }
            #pragma unroll
            for (int nb = 0; nb < 8; nb++)
                mma_s8(accP[nb], Ad1, Bd1[nb>>1][(nb&1)*2], Bd1[nb>>1][(nb&1)*2+1]);
            #pragma unroll
            for (int nb = 0; nb < 8; nb++)
                mma_s8(accX[nb], Ad1, Bd2[nb>>1][(nb&1)*2], Bd2[nb>>1][(nb&1)*2+1]);
            #pragma unroll
            for (int nb = 0; nb < 8; nb++)
                mma_s8(accX[nb], Ad2, Bd1[nb>>1][(nb&1)*2], Bd1[nb>>1][(nb&1)*2+1]);
        }

        // ---- reconstruct scores + online softmax ----
        float sacc[8][4];
        #pragma unroll
        for (int nb = 0; nb < 8; nb++) {
            const int col = nb*8 + (lane & 3) * 2;
            const float k0 = skf[col] * scale, k1 = skf[col + 1] * scale;
            sacc[nb][0] = sq0 * k0 * ((float)accP[nb][0] + (float)accX[nb][0] * 0.004f);
            sacc[nb][1] = sq0 * k1 * ((float)accP[nb][1] + (float)accX[nb][1] * 0.004f);
            sacc[nb][2] = sq1 * k0 * ((float)accP[nb][2] + (float)accX[nb][2] * 0.004f);
            sacc[nb][3] = sq1 * k1 * ((float)accP[nb][3] + (float)accX[nb][3] * 0.004f);
        }

        float mx0 = -1e30f, mx1 = -1e30f;
        #pragma unroll
        for (int nb = 0; nb < 8; nb++) {
            mx0 = fmaxf(mx0, fmaxf(sacc[nb][0], sacc[nb][1]));
            mx1 = fmaxf(mx1, fmaxf(sacc[nb][2], sacc[nb][3]));
        }
        mx0 = fmaxf(mx0, __shfl_xor_sync(0xffffffffu, mx0, 1));
        mx0 = fmaxf(mx0, __shfl_xor_sync(0xffffffffu, mx0, 2));
        mx1 = fmaxf(mx1, __shfl_xor_sync(0xffffffffu, mx1, 1));
        mx1 = fmaxf(mx1, __shfl_xor_sync(0xffffffffu, mx1, 2));

        const float mn0 = fmaxf(m0, mx0), mn1 = fmaxf(m1, mx1);
        const float al0 = __expf(m0 - mn0), al1 = __expf(m1 - mn1);
        m0 = mn0; m1 = mn1;

        float rs0 = 0.f, rs1 = 0.f;
        #pragma unroll
        for (int nb = 0; nb < 8; nb++) {
            sacc[nb][0] = __expf(sacc[nb][0] - m0);
            sacc[nb][1] = __expf(sacc[nb][1] - m0);
            sacc[nb][2] = __expf(sacc[nb][2] - m1);
            sacc[nb][3] = __expf(sacc[nb][3] - m1);
            rs0 += sacc[nb][0] + sacc[nb][1];
            rs1 += sacc[nb][2] + sacc[nb][3];
        }
        rs0 += __shfl_xor_sync(0xffffffffu, rs0, 1);
        rs0 += __shfl_xor_sync(0xffffffffu, rs0, 2);
        rs1 += __shfl_xor_sync(0xffffffffu, rs1, 1);
        rs1 += __shfl_xor_sync(0xffffffffu, rs1, 2);
        l0 = l0 * al0 + rs0;
        l1 = l1 * al1 + rs1;

        #pragma unroll
        for (int nb = 0; nb < 10; nb++) {
            oacc[nb][0] *= al0; oacc[nb][1] *= al0;
            oacc[nb][2] *= al1; oacc[nb][3] *= al1;
        }

        // ---- O += P @ V, bf16 3-pass ----
        #pragma unroll
        for (int kc = 0; kc < 4; kc++) {
            uint32_t Pa_h[4], Pa_l[4];
            #pragma unroll
            for (int half2i = 0; half2i < 2; half2i++) {
                const int nb = 2*kc + half2i;
                float f0 = sacc[nb][0], f1 = sacc[nb][1];
                float f2 = sacc[nb][2], f3 = sacc[nb][3];
                float h0 = __bfloat162float(__float2bfloat16_rn(f0));
                float h1 = __bfloat162float(__float2bfloat16_rn(f1));
                float h2 = __bfloat162float(__float2bfloat16_rn(f2));
                float h3 = __bfloat162float(__float2bfloat16_rn(f3));
                Pa_h[2*half2i+0] = packbf(h0, h1);
                Pa_h[2*half2i+1] = packbf(h2, h3);
                Pa_l[2*half2i+0] = packbf(f0 - h0, f1 - h1);
                Pa_l[2*half2i+1] = packbf(f2 - h2, f3 - h3);
            }
            uint32_t Vh4[5][4], Vl4[5][4];
            #pragma unroll
            for (int vg = 0; vg < 5; vg++) {
                const int vrow = kc*16 + ((lane >> 3) & 1) * 8 + (lane & 7);
                const int vcol = vg*16 + (lane >> 4) * 8;
                const uint32_t voff = (uint32_t)(vrow * APITCH + vcol * 2);
                ldm_x4_t(Vh4[vg], kvb + SVHo + voff);
                ldm_x4_t(Vl4[vg], kvb + SVLo + voff);
            }
            #pragma unroll
            for (int vg = 0; vg < 5; vg++)
                #pragma unroll
                for (int hh = 0; hh < 2; hh++)
                    mma16816(oacc[vg*2+hh], Pa_h, Vh4[vg][2*hh], Vh4[vg][2*hh+1]);
            #pragma unroll
            for (int vg = 0; vg < 5; vg++)
                #pragma unroll
                for (int hh = 0; hh < 2; hh++)
                    mma16816(oacc[vg*2+hh], Pa_l, Vh4[vg][2*hh], Vh4[vg][2*hh+1]);
            #pragma unroll
            for (int vg = 0; vg < 5; vg++)
                #pragma unroll
                for (int hh = 0; hh < 2; hh++)
                    mma16816(oacc[vg*2+hh], Pa_h, Vl4[vg][2*hh], Vl4[vg][2*hh+1]);
        }
        __syncthreads();
    }

    // ---- finalize: normalize, write fp32 ctx ----
    const float inv0 = 1.f / l0, inv1 = 1.f / l1;
    const int s0 = qt*128 + w*16 + (lane >> 2);
    const int s1 = s0 + 8;
    #pragma unroll
    for (int nb = 0; nb < 10; nb++) {
        const int d = nb*8 + (lane & 3) * 2;
        {
            float2 v; v.x = oacc[nb][0] * inv0; v.y = oacc[nb][1] * inv0;
            *(float2*)&g_ctx[((size_t)b * SQ + s0) * DM + h * HD + d] = v;
        }
        {
            float2 v; v.x = oacc[nb][2] * inv1; v.y = oacc[nb][3] * inv1;
            *(float2*)&g_ctx[((size_t)b * SQ + s1) * DM + h * HD + d] = v;
        }
    }
}

// ---------------------------------------------------------------------------
extern "C" void kernel_launch(void* const* d_in, const int* in_sizes, int n_in,
                              void* d_out, int out_size)
{
    (void)in_sizes; (void)n_in; (void)out_size;
    const float* x     = (const float*)d_in[0];
    const float* cosp  = (const float*)d_in[1];
    const float* sinp  = (const float*)d_in[2];
    const float* Wqkv  = (const float*)d_in[3];
    const float* bqkv  = (const float*)d_in[4];
    const float* Wproj = (const float*)d_in[5];
    const float* bproj = (const float*)d_in[6];
    float* out = (float*)d_out;

    cudaFuncSetAttribute(gemm_i8<false>,
                         cudaFuncAttributeMaxDynamicSharedMemorySize, IGEMM_DSMEM);
    cudaFuncSetAttribute(gemm_i8<true>,
                         cudaFuncAttributeMaxDynamicSharedMemorySize, IGEMM_DSMEM);
    cudaFuncSetAttribute(attn_tc,
                         cudaFuncAttributeMaxDynamicSharedMemorySize, ATTN_SMEM);

    int8_t *xq1, *xq2, *wq1, *wq2;
    float *sax, *sbw, *ctx;
    cudaGetSymbolAddress((void**)&xq1, xq1_g);
    cudaGetSymbolAddress((void**)&xq2, xq2_g);
    cudaGetSymbolAddress((void**)&wq1, wq1_g);
    cudaGetSymbolAddress((void**)&wq2, wq2_g);
    cudaGetSymbolAddress((void**)&sax, sax_g);
    cudaGetSymbolAddress((void**)&sbw, sbw_g);
    cudaGetSymbolAddress((void**)&ctx, g_ctx);

    // 0) quantize x, Wqkv
    quant_kernel<<<MTOT, 128>>>(x, xq1, xq2, sax);
    quant_kernel<<<NQKV, 128>>>(Wqkv, wq1, wq2, sbw);
    // 1) QKV GEMM (int8): q,k fp32 head-major + v bf16 hi/lo
    gemm_i8<false><<<dim3(NQKV/64, MTOT/128), 256, IGEMM_DSMEM>>>(
        xq1, xq2, wq1, wq2, sax, sbw, bqkv, nullptr);
    // 2) RoPE + int8 quant -> qq/kq + scales
    rope_quant<<<NROWS/8, 256>>>(cosp, sinp);
    // 3) attention (int8 S, bf16 PV) -> fp32 ctx
    attn_tc<<<dim3(SQ/128, NB*NH), 256, ATTN_SMEM>>>();
    // 4) re-quantize ctx and Wproj (reusing x/w digit buffers)
    quant_kernel<<<MTOT, 128>>>(ctx, xq1, xq2, sax);
    quant_kernel<<<DM, 128>>>(Wproj, wq1, wq2, sbw);
    // 5) output projection (int8) -> d_out
    gemm_i8<true><<<dim3(DM/64, MTOT/128), 256, IGEMM_DSMEM>>>(
        xq1, xq2, wq1, wq2, sax, sbw, bproj, out);
}